// round 5
// baseline (speedup 1.0000x reference)
#include <cuda_runtime.h>
#include <math.h>

// Problem constants
#define BB   2
#define TT   4096
#define CC   1024
#define HH   8
#define DD   128
#define WIN  512
#define MM   (BB*TT)          // 8192 rows
#define N3C  (3*CC)           // 3072

// Scratch (device globals: allocation-free per harness rules)
__device__ float g_q [BB*HH*TT*DD];   // [bh][t][d]
__device__ float g_k [BB*HH*TT*DD];   // [bh][t][d]
__device__ float g_v [BB*HH*TT*DD];   // [bh][t][d]
__device__ float g_ao[BB*TT*HH*DD];   // [b][t][h][d]  == [M][C] row-major

// ---------------------------------------------------------------------------
// Kernel 1: qkv = x @ w_qkv^T  (M=8192, N=3072, K=1024), scatter to q/k/v.
// 128x128x16 tiles, 256 threads, 8x8 micro-tile.
// ---------------------------------------------------------------------------
__global__ __launch_bounds__(256)
void qkv_gemm(const float* __restrict__ A, const float* __restrict__ W) {
    __shared__ float As[16][128];
    __shared__ float Bs[16][128];
    const int K = CC;
    const int bx = blockIdx.x;          // 0..23  (N tiles)
    const int by = blockIdx.y;          // 0..63  (M tiles)
    const int tid = threadIdx.x;
    const int tx = tid & 15, ty = tid >> 4;

    const float* Ab = A + (size_t)by * 128 * K;
    const float* Wb = W + (size_t)bx * 128 * K;

    float acc[8][8];
    #pragma unroll
    for (int i = 0; i < 8; ++i)
        #pragma unroll
        for (int j = 0; j < 8; ++j) acc[i][j] = 0.f;

    const int lrow = tid >> 2;          // 0..63
    const int lcol = (tid & 3) << 2;    // 0,4,8,12

    for (int k0 = 0; k0 < K; k0 += 16) {
        #pragma unroll
        for (int p = 0; p < 2; ++p) {
            const int r = lrow + p * 64;
            float4 va = *(const float4*)(Ab + (size_t)r * K + k0 + lcol);
            As[lcol + 0][r] = va.x; As[lcol + 1][r] = va.y;
            As[lcol + 2][r] = va.z; As[lcol + 3][r] = va.w;
            float4 vb = *(const float4*)(Wb + (size_t)r * K + k0 + lcol);
            Bs[lcol + 0][r] = vb.x; Bs[lcol + 1][r] = vb.y;
            Bs[lcol + 2][r] = vb.z; Bs[lcol + 3][r] = vb.w;
        }
        __syncthreads();
        #pragma unroll
        for (int kk = 0; kk < 16; ++kk) {
            float4 a0 = *(const float4*)&As[kk][ty * 8];
            float4 a1 = *(const float4*)&As[kk][ty * 8 + 4];
            float4 b0 = *(const float4*)&Bs[kk][tx * 8];
            float4 b1 = *(const float4*)&Bs[kk][tx * 8 + 4];
            float ra[8] = {a0.x,a0.y,a0.z,a0.w,a1.x,a1.y,a1.z,a1.w};
            float rb[8] = {b0.x,b0.y,b0.z,b0.w,b1.x,b1.y,b1.z,b1.w};
            #pragma unroll
            for (int i = 0; i < 8; ++i)
                #pragma unroll
                for (int j = 0; j < 8; ++j)
                    acc[i][j] = fmaf(ra[i], rb[j], acc[i][j]);
        }
        __syncthreads();
    }

    // Epilogue: N-tile bx is exactly one (section, head): sec = bx/8, h = bx%8
    const int sec = bx >> 3;
    const int h   = bx & 7;
    float* dst = (sec == 0) ? g_q : ((sec == 1) ? g_k : g_v);
    #pragma unroll
    for (int i = 0; i < 8; ++i) {
        const int m = by * 128 + ty * 8 + i;
        const int b = m >> 12;              // /4096
        const int t = m & (TT - 1);
        float* row = dst + (((size_t)(b * HH + h) * TT + t) * DD) + tx * 8;
        *(float4*)(row)     = make_float4(acc[i][0], acc[i][1], acc[i][2], acc[i][3]);
        *(float4*)(row + 4) = make_float4(acc[i][4], acc[i][5], acc[i][6], acc[i][7]);
    }
}

// ---------------------------------------------------------------------------
// Kernel 2: RoPE in-place on g_q, g_k. One thread per (bh, t, dim-pair i).
// out[i]    = x[i]*cos - x[i+64]*sin ;  out[i+64] = x[i+64]*cos + x[i]*sin
// ---------------------------------------------------------------------------
__global__ __launch_bounds__(256)
void rope_kernel() {
    const int idx = blockIdx.x * blockDim.x + threadIdx.x;   // < BB*HH*TT*64
    const int i  = idx & 63;
    const int t  = (idx >> 6) & (TT - 1);
    const int bh = idx >> 18;
    if (bh >= BB * HH) return;

    const float inv_freq = 1.0f / powf(10000.0f, (float)(2 * i) / 128.0f);
    float s, c;
    sincosf((float)t * inv_freq, &s, &c);

    const size_t base = ((size_t)bh * TT + t) * DD;
    float q0 = g_q[base + i], q1 = g_q[base + i + 64];
    g_q[base + i]      = q0 * c - q1 * s;
    g_q[base + i + 64] = q1 * c + q0 * s;
    float k0 = g_k[base + i], k1 = g_k[base + i + 64];
    g_k[base + i]      = k0 * c - k1 * s;
    g_k[base + i + 64] = k1 * c + k0 * s;
}

// ---------------------------------------------------------------------------
// Kernel 3: sliding-window causal flash attention.
// Block = (q-tile of 64, bh). 256 threads. KV chunks of 64. Online softmax.
// smem: Qs[64][128], KsT[128][68] (transposed K, pad for conflict-free LDS),
//       Vs[64][128], Ps[64][64].
// ---------------------------------------------------------------------------
#define ATTN_SMEM_FLOATS (64*128 + 128*68 + 64*128 + 64*64)
#define ATTN_SMEM_BYTES  (ATTN_SMEM_FLOATS * 4)

__global__ __launch_bounds__(256)
void attn_kernel() {
    extern __shared__ float sm[];
    float* Qs  = sm;                    // [64][128]
    float* KsT = Qs + 64 * 128;         // [128][68]
    float* Vs  = KsT + 128 * 68;        // [64][128]
    float* Ps  = Vs + 64 * 128;         // [64][64]

    const int qb = blockIdx.x;          // 0..63
    const int bh = blockIdx.y;          // 0..15
    const int q0 = qb << 6;
    const int tid = threadIdx.x;
    const int tx = tid & 15, ty = tid >> 4;
    const float scale = 0.08838834764831845f;   // 1/sqrt(128)

    // Load Q tile
    const float* Qg = g_q + ((size_t)bh * TT + q0) * DD;
    for (int i = tid; i < 64 * 128 / 4; i += 256)
        ((float4*)Qs)[i] = ((const float4*)Qg)[i];

    float mrow[4], lrow[4], O[4][8];
    #pragma unroll
    for (int i = 0; i < 4; ++i) {
        mrow[i] = -1e30f; lrow[i] = 0.f;
        #pragma unroll
        for (int j = 0; j < 8; ++j) O[i][j] = 0.f;
    }

    const int r0 = ty << 2;    // 4 query rows for this thread
    const int c0 = tx << 2;    // 4 key cols (S stage)
    const int oc = tx << 3;    // 8 output dims (O stage)

    int cb0 = qb - (WIN >> 6); if (cb0 < 0) cb0 = 0;

    for (int cb = cb0; cb <= qb; ++cb) {
        __syncthreads();   // previous O-stage done with Ks/Vs/Ps
        const float* Kg = g_k + ((size_t)bh * TT + (cb << 6)) * DD;
        const float* Vg = g_v + ((size_t)bh * TT + (cb << 6)) * DD;
        #pragma unroll
        for (int i = tid; i < 64 * 32; i += 256) {
            const int r  = i >> 5;            // key row 0..63
            const int c4 = (i & 31) << 2;     // dim 0..124
            float4 kv4 = *(const float4*)(Kg + r * DD + c4);
            KsT[(c4 + 0) * 68 + r] = kv4.x;
            KsT[(c4 + 1) * 68 + r] = kv4.y;
            KsT[(c4 + 2) * 68 + r] = kv4.z;
            KsT[(c4 + 3) * 68 + r] = kv4.w;
            ((float4*)Vs)[i] = ((const float4*)Vg)[i];
        }
        __syncthreads();

        // S = Q K^T for this thread's 4x4 tile
        float s[4][4];
        #pragma unroll
        for (int i = 0; i < 4; ++i)
            #pragma unroll
            for (int j = 0; j < 4; ++j) s[i][j] = 0.f;

        #pragma unroll 4
        for (int kk = 0; kk < 128; kk += 4) {
            float4 qv[4], kv[4];
            #pragma unroll
            for (int i = 0; i < 4; ++i)
                qv[i] = *(const float4*)&Qs[(r0 + i) * 128 + kk];
            #pragma unroll
            for (int u = 0; u < 4; ++u)
                kv[u] = *(const float4*)&KsT[(kk + u) * 68 + c0];
            #pragma unroll
            for (int i = 0; i < 4; ++i) {
                s[i][0] += qv[i].x*kv[0].x + qv[i].y*kv[1].x + qv[i].z*kv[2].x + qv[i].w*kv[3].x;
                s[i][1] += qv[i].x*kv[0].y + qv[i].y*kv[1].y + qv[i].z*kv[2].y + qv[i].w*kv[3].y;
                s[i][2] += qv[i].x*kv[0].z + qv[i].y*kv[1].z + qv[i].z*kv[2].z + qv[i].w*kv[3].z;
                s[i][3] += qv[i].x*kv[0].w + qv[i].y*kv[1].w + qv[i].z*kv[2].w + qv[i].w*kv[3].w;
            }
        }

        // Mask, online softmax (row groups = 16 consecutive lanes)
        const int kbase = cb << 6;
        float corr[4];
        #pragma unroll
        for (int i = 0; i < 4; ++i) {
            const int qi = q0 + r0 + i;
            #pragma unroll
            for (int j = 0; j < 4; ++j) {
                const int kj = kbase + c0 + j;
                const bool keep = (kj <= qi) && (kj + WIN >= qi);
                s[i][j] = keep ? s[i][j] * scale : -1e30f;
            }
            float rm = fmaxf(fmaxf(s[i][0], s[i][1]), fmaxf(s[i][2], s[i][3]));
            rm = fmaxf(rm, __shfl_xor_sync(0xffffffffu, rm, 1, 16));
            rm = fmaxf(rm, __shfl_xor_sync(0xffffffffu, rm, 2, 16));
            rm = fmaxf(rm, __shfl_xor_sync(0xffffffffu, rm, 4, 16));
            rm = fmaxf(rm, __shfl_xor_sync(0xffffffffu, rm, 8, 16));
            const float mnew = fmaxf(mrow[i], rm);
            corr[i] = __expf(mrow[i] - mnew);
            mrow[i] = mnew;
            float rs = 0.f;
            #pragma unroll
            for (int j = 0; j < 4; ++j) {
                const float p = __expf(s[i][j] - mnew);
                Ps[(r0 + i) * 64 + c0 + j] = p;
                rs += p;
            }
            rs += __shfl_xor_sync(0xffffffffu, rs, 1, 16);
            rs += __shfl_xor_sync(0xffffffffu, rs, 2, 16);
            rs += __shfl_xor_sync(0xffffffffu, rs, 4, 16);
            rs += __shfl_xor_sync(0xffffffffu, rs, 8, 16);
            lrow[i] = lrow[i] * corr[i] + rs;
        }
        __syncthreads();   // Ps visible to all

        // O = O*corr + P @ V  (this thread: 4 rows x 8 dims)
        #pragma unroll
        for (int i = 0; i < 4; ++i)
            #pragma unroll
            for (int j = 0; j < 8; ++j) O[i][j] *= corr[i];

        #pragma unroll 4
        for (int kk = 0; kk < 64; ++kk) {
            float4 v0 = *(const float4*)&Vs[kk * 128 + oc];
            float4 v1 = *(const float4*)&Vs[kk * 128 + oc + 4];
            #pragma unroll
            for (int i = 0; i < 4; ++i) {
                const float p = Ps[(r0 + i) * 64 + kk];
                O[i][0] += p * v0.x; O[i][1] += p * v0.y;
                O[i][2] += p * v0.z; O[i][3] += p * v0.w;
                O[i][4] += p * v1.x; O[i][5] += p * v1.y;
                O[i][6] += p * v1.z; O[i][7] += p * v1.w;
            }
        }
    }

    // Normalize and write to [b][t][h][d] (= [M][C] for the output GEMM)
    const int b = bh >> 3, h = bh & 7;
    #pragma unroll
    for (int i = 0; i < 4; ++i) {
        const float inv = 1.0f / lrow[i];
        const int t = q0 + r0 + i;
        float* dst = g_ao + (((size_t)(b * TT + t) * HH) + h) * DD + oc;
        *(float4*)(dst)     = make_float4(O[i][0]*inv, O[i][1]*inv, O[i][2]*inv, O[i][3]*inv);
        *(float4*)(dst + 4) = make_float4(O[i][4]*inv, O[i][5]*inv, O[i][6]*inv, O[i][7]*inv);
    }
}

// ---------------------------------------------------------------------------
// Kernel 4: out = attn_out @ w_o^T  (M=8192, N=1024, K=1024)
// ---------------------------------------------------------------------------
__global__ __launch_bounds__(256)
void out_gemm(const float* __restrict__ W, float* __restrict__ out) {
    __shared__ float As[16][128];
    __shared__ float Bs[16][128];
    const int K = CC;
    const int bx = blockIdx.x;          // 0..7
    const int by = blockIdx.y;          // 0..63
    const int tid = threadIdx.x;
    const int tx = tid & 15, ty = tid >> 4;

    const float* Ab = g_ao + (size_t)by * 128 * K;
    const float* Wb = W + (size_t)bx * 128 * K;

    float acc[8][8];
    #pragma unroll
    for (int i = 0; i < 8; ++i)
        #pragma unroll
        for (int j = 0; j < 8; ++j) acc[i][j] = 0.f;

    const int lrow = tid >> 2;
    const int lcol = (tid & 3) << 2;

    for (int k0 = 0; k0 < K; k0 += 16) {
        #pragma unroll
        for (int p = 0; p < 2; ++p) {
            const int r = lrow + p * 64;
            float4 va = *(const float4*)(Ab + (size_t)r * K + k0 + lcol);
            As[lcol + 0][r] = va.x; As[lcol + 1][r] = va.y;
            As[lcol + 2][r] = va.z; As[lcol + 3][r] = va.w;
            float4 vb = *(const float4*)(Wb + (size_t)r * K + k0 + lcol);
            Bs[lcol + 0][r] = vb.x; Bs[lcol + 1][r] = vb.y;
            Bs[lcol + 2][r] = vb.z; Bs[lcol + 3][r] = vb.w;
        }
        __syncthreads();
        #pragma unroll
        for (int kk = 0; kk < 16; ++kk) {
            float4 a0 = *(const float4*)&As[kk][ty * 8];
            float4 a1 = *(const float4*)&As[kk][ty * 8 + 4];
            float4 b0 = *(const float4*)&Bs[kk][tx * 8];
            float4 b1 = *(const float4*)&Bs[kk][tx * 8 + 4];
            float ra[8] = {a0.x,a0.y,a0.z,a0.w,a1.x,a1.y,a1.z,a1.w};
            float rb[8] = {b0.x,b0.y,b0.z,b0.w,b1.x,b1.y,b1.z,b1.w};
            #pragma unroll
            for (int i = 0; i < 8; ++i)
                #pragma unroll
                for (int j = 0; j < 8; ++j)
                    acc[i][j] = fmaf(ra[i], rb[j], acc[i][j]);
        }
        __syncthreads();
    }

    #pragma unroll
    for (int i = 0; i < 8; ++i) {
        const int m = by * 128 + ty * 8 + i;
        float* row = out + (size_t)m * CC + bx * 128 + tx * 8;
        *(float4*)(row)     = make_float4(acc[i][0], acc[i][1], acc[i][2], acc[i][3]);
        *(float4*)(row + 4) = make_float4(acc[i][4], acc[i][5], acc[i][6], acc[i][7]);
    }
}

// ---------------------------------------------------------------------------
extern "C" void kernel_launch(void* const* d_in, const int* in_sizes, int n_in,
                              void* d_out, int out_size) {
    const float* x     = (const float*)d_in[0];   // [2,4096,1024]
    const float* w_qkv = (const float*)d_in[1];   // [3072,1024]
    const float* w_o   = (const float*)d_in[2];   // [1024,1024]
    float* out = (float*)d_out;                   // [2,4096,1024]

    cudaFuncSetAttribute(attn_kernel,
                         cudaFuncAttributeMaxDynamicSharedMemorySize,
                         ATTN_SMEM_BYTES);

    qkv_gemm<<<dim3(N3C / 128, MM / 128), 256>>>(x, w_qkv);
    rope_kernel<<<(BB * HH * TT * 64) / 256, 256>>>();
    attn_kernel<<<dim3(TT / 64, BB * HH), 256, ATTN_SMEM_BYTES>>>();
    out_gemm<<<dim3(CC / 128, MM / 128), 256>>>(w_o, out);
}

// round 9
// speedup vs baseline: 1.4649x; 1.4649x over previous
#include <cuda_runtime.h>
#include <cuda_bf16.h>
#include <cstdint>
#include <math.h>

// Problem constants
#define BB   2
#define TT   4096
#define CC   1024
#define HH   8
#define DD   128
#define WIN  512
#define MM   (BB*TT)          // 8192 rows
#define N3C  (3*CC)           // 3072

// ---------------------------------------------------------------------------
// Scratch (device globals: allocation-free per harness rules)
// ---------------------------------------------------------------------------
__device__ float g_q [BB*HH*TT*DD];   // [bh][t][d]
__device__ float g_k [BB*HH*TT*DD];   // [bh][t][d]
__device__ float g_v [BB*HH*TT*DD];   // [bh][t][d]
__device__ float g_ao[BB*TT*HH*DD];   // [b][t][h][d]  == [M][C] row-major

// bf16 hi/lo split operands for tensor-core GEMMs
__device__ __nv_bfloat16 g_xh [MM*CC],  g_xl [MM*CC];
__device__ __nv_bfloat16 g_wqh[N3C*CC], g_wql[N3C*CC];
__device__ __nv_bfloat16 g_woh[CC*CC],  g_wol[CC*CC];
__device__ __nv_bfloat16 g_aoh[MM*CC],  g_aol[MM*CC];

// ---------------------------------------------------------------------------
// fp32 -> (bf16 hi, bf16 lo) split.  x ~= hi + lo, |residual| ~ 2^-17 |x|
// ---------------------------------------------------------------------------
__global__ __launch_bounds__(256)
void split_bf16(const float* __restrict__ src,
                __nv_bfloat16* __restrict__ hi,
                __nv_bfloat16* __restrict__ lo, int n4) {
    const int i = blockIdx.x * blockDim.x + threadIdx.x;
    if (i >= n4) return;
    float4 v = ((const float4*)src)[i];
    __nv_bfloat16 h0 = __float2bfloat16_rn(v.x);
    __nv_bfloat16 h1 = __float2bfloat16_rn(v.y);
    __nv_bfloat16 h2 = __float2bfloat16_rn(v.z);
    __nv_bfloat16 h3 = __float2bfloat16_rn(v.w);
    __nv_bfloat16 l0 = __float2bfloat16_rn(v.x - __bfloat162float(h0));
    __nv_bfloat16 l1 = __float2bfloat16_rn(v.y - __bfloat162float(h1));
    __nv_bfloat16 l2 = __float2bfloat16_rn(v.z - __bfloat162float(h2));
    __nv_bfloat16 l3 = __float2bfloat16_rn(v.w - __bfloat162float(h3));
    union { __nv_bfloat16 b[4]; uint2 u; } H, L;
    H.b[0]=h0; H.b[1]=h1; H.b[2]=h2; H.b[3]=h3;
    L.b[0]=l0; L.b[1]=l1; L.b[2]=l2; L.b[3]=l3;
    ((uint2*)hi)[i] = H.u;
    ((uint2*)lo)[i] = L.u;
}

// ---------------------------------------------------------------------------
// Tensor-core GEMM: C = A @ W^T with fp32 accuracy via 3-term bf16 split.
//   A: [M][1024] (hi/lo), W: [N][1024] (hi/lo)
// Block tile 128x128, BK=32. 8 warps (2 M x 4 N), warp tile 64x32,
// mma.sync.m16n8k16 bf16, fragments via direct conflict-free LDS.
// EPI=0: qkv scatter to g_q/g_k/g_v (N=3072).  EPI=1: plain store (N=1024).
// ---------------------------------------------------------------------------
#define SROW 40    // padded smem row stride in bf16 (bank-conflict-free)

#define MMA16816(d, a, b0_, b1_)                                          \
    asm volatile("mma.sync.aligned.m16n8k16.row.col.f32.bf16.bf16.f32 "   \
        "{%0,%1,%2,%3}, {%4,%5,%6,%7}, {%8,%9}, {%0,%1,%2,%3};"           \
        : "+f"(d[0]), "+f"(d[1]), "+f"(d[2]), "+f"(d[3])                  \
        : "r"(a[0]), "r"(a[1]), "r"(a[2]), "r"(a[3]), "r"(b0_), "r"(b1_))

#define SMU32(arr, r, c) (*reinterpret_cast<const unsigned*>(&(arr)[(r)*SROW + (c)]))

template<int EPI>
__global__ __launch_bounds__(256, 1)
void gemm_bf16(float* __restrict__ Out) {
    __shared__ __nv_bfloat16 sAh[128*SROW];
    __shared__ __nv_bfloat16 sAl[128*SROW];
    __shared__ __nv_bfloat16 sBh[128*SROW];
    __shared__ __nv_bfloat16 sBl[128*SROW];

    const __nv_bfloat16* __restrict__ Ah = (EPI == 0) ? g_xh  : g_aoh;
    const __nv_bfloat16* __restrict__ Al = (EPI == 0) ? g_xl  : g_aol;
    const __nv_bfloat16* __restrict__ Bh = (EPI == 0) ? g_wqh : g_woh;
    const __nv_bfloat16* __restrict__ Bl = (EPI == 0) ? g_wql : g_wol;

    const int bx = blockIdx.x;              // N tile
    const int by = blockIdx.y;              // M tile
    const int tid = threadIdx.x;
    const int warp = tid >> 5, lane = tid & 31;
    const int wm = warp >> 2, wn = warp & 3;        // 2 x 4 warp grid
    const int group = lane >> 2, tg = lane & 3;

    float acc[4][4][4];
    #pragma unroll
    for (int mt = 0; mt < 4; ++mt)
        #pragma unroll
        for (int nt = 0; nt < 4; ++nt)
            #pragma unroll
            for (int e = 0; e < 4; ++e) acc[mt][nt][e] = 0.f;

    const size_t arow = (size_t)by * 128 * 1024;
    const size_t brow = (size_t)bx * 128 * 1024;

    for (int k0 = 0; k0 < 1024; k0 += 32) {
        // ---- load A(hi,lo) and B(hi,lo) tiles: 128 rows x 32 bf16 each ----
        #pragma unroll
        for (int it = 0; it < 2; ++it) {
            const int s  = tid + it * 256;          // 0..511
            const int r  = s >> 2;
            const int kk = (s & 3) << 3;            // 0,8,16,24
            const size_t ga = arow + (size_t)r * 1024 + k0 + kk;
            const size_t gb = brow + (size_t)r * 1024 + k0 + kk;
            *(uint4*)&sAh[r*SROW + kk] = *(const uint4*)&Ah[ga];
            *(uint4*)&sAl[r*SROW + kk] = *(const uint4*)&Al[ga];
            *(uint4*)&sBh[r*SROW + kk] = *(const uint4*)&Bh[gb];
            *(uint4*)&sBl[r*SROW + kk] = *(const uint4*)&Bl[gb];
        }
        __syncthreads();

        #pragma unroll
        for (int ks = 0; ks < 32; ks += 16) {
            // A fragments for 4 m-tiles, hi and lo
            unsigned fah[4][4], fal[4][4];
            #pragma unroll
            for (int mt = 0; mt < 4; ++mt) {
                const int r = wm*64 + mt*16 + group;
                const int c = ks + 2*tg;
                fah[mt][0] = SMU32(sAh, r,     c);
                fah[mt][1] = SMU32(sAh, r + 8, c);
                fah[mt][2] = SMU32(sAh, r,     c + 8);
                fah[mt][3] = SMU32(sAh, r + 8, c + 8);
                fal[mt][0] = SMU32(sAl, r,     c);
                fal[mt][1] = SMU32(sAl, r + 8, c);
                fal[mt][2] = SMU32(sAl, r,     c + 8);
                fal[mt][3] = SMU32(sAl, r + 8, c + 8);
            }
            #pragma unroll
            for (int nt = 0; nt < 4; ++nt) {
                const int n = wn*32 + nt*8 + group;
                const int c = ks + 2*tg;
                const unsigned bh0 = SMU32(sBh, n, c);
                const unsigned bh1 = SMU32(sBh, n, c + 8);
                const unsigned bl0 = SMU32(sBl, n, c);
                const unsigned bl1 = SMU32(sBl, n, c + 8);
                #pragma unroll
                for (int mt = 0; mt < 4; ++mt) {
                    MMA16816(acc[mt][nt], fah[mt], bh0, bh1);
                    MMA16816(acc[mt][nt], fah[mt], bl0, bl1);
                    MMA16816(acc[mt][nt], fal[mt], bh0, bh1);
                }
            }
        }
        __syncthreads();
    }

    // ---- epilogue ----
    // fragment D: d0,d1 -> (row=group, col=2tg,2tg+1); d2,d3 -> row=group+8
    if (EPI == 0) {
        const int sec = bx >> 3;
        const int h   = bx & 7;
        float* dst = (sec == 0) ? g_q : ((sec == 1) ? g_k : g_v);
        #pragma unroll
        for (int mt = 0; mt < 4; ++mt) {
            const int m = by*128 + wm*64 + mt*16 + group;
            const int b = m >> 12;
            const int t = m & (TT - 1);
            const size_t rbase = ((size_t)(b * HH + h) * TT + t) * DD;
            #pragma unroll
            for (int nt = 0; nt < 4; ++nt) {
                const int d = wn*32 + nt*8 + tg*2;
                *(float2*)&dst[rbase + d] =
                    make_float2(acc[mt][nt][0], acc[mt][nt][1]);
                *(float2*)&dst[rbase + 8*DD + d] =
                    make_float2(acc[mt][nt][2], acc[mt][nt][3]);
            }
        }
    } else {
        #pragma unroll
        for (int mt = 0; mt < 4; ++mt) {
            const int m = by*128 + wm*64 + mt*16 + group;
            #pragma unroll
            for (int nt = 0; nt < 4; ++nt) {
                const int n = bx*128 + wn*32 + nt*8 + tg*2;
                *(float2*)&Out[(size_t)m * CC + n] =
                    make_float2(acc[mt][nt][0], acc[mt][nt][1]);
                *(float2*)&Out[(size_t)(m + 8) * CC + n] =
                    make_float2(acc[mt][nt][2], acc[mt][nt][3]);
            }
        }
    }
}

// ---------------------------------------------------------------------------
// RoPE in-place on g_q, g_k. One thread per (bh, t, dim-pair i).
// ---------------------------------------------------------------------------
__global__ __launch_bounds__(256)
void rope_kernel() {
    const int idx = blockIdx.x * blockDim.x + threadIdx.x;   // < BB*HH*TT*64
    const int i  = idx & 63;
    const int t  = (idx >> 6) & (TT - 1);
    const int bh = idx >> 18;
    if (bh >= BB * HH) return;

    const float inv_freq = 1.0f / powf(10000.0f, (float)(2 * i) / 128.0f);
    float s, c;
    sincosf((float)t * inv_freq, &s, &c);

    const size_t base = ((size_t)bh * TT + t) * DD;
    float q0 = g_q[base + i], q1 = g_q[base + i + 64];
    g_q[base + i]      = q0 * c - q1 * s;
    g_q[base + i + 64] = q1 * c + q0 * s;
    float k0 = g_k[base + i], k1 = g_k[base + i + 64];
    g_k[base + i]      = k0 * c - k1 * s;
    g_k[base + i + 64] = k1 * c + k0 * s;
}

// ---------------------------------------------------------------------------
// Sliding-window causal flash attention (unchanged from passing baseline).
// ---------------------------------------------------------------------------
#define ATTN_SMEM_FLOATS (64*128 + 128*68 + 64*128 + 64*64)
#define ATTN_SMEM_BYTES  (ATTN_SMEM_FLOATS * 4)

__global__ __launch_bounds__(256)
void attn_kernel() {
    extern __shared__ float sm[];
    float* Qs  = sm;                    // [64][128]
    float* KsT = Qs + 64 * 128;         // [128][68]
    float* Vs  = KsT + 128 * 68;        // [64][128]
    float* Ps  = Vs + 64 * 128;         // [64][64]

    const int qb = blockIdx.x;          // 0..63
    const int bh = blockIdx.y;          // 0..15
    const int q0 = qb << 6;
    const int tid = threadIdx.x;
    const int tx = tid & 15, ty = tid >> 4;
    const float scale = 0.08838834764831845f;   // 1/sqrt(128)

    const float* Qg = g_q + ((size_t)bh * TT + q0) * DD;
    for (int i = tid; i < 64 * 128 / 4; i += 256)
        ((float4*)Qs)[i] = ((const float4*)Qg)[i];

    float mrow[4], lrow[4], O[4][8];
    #pragma unroll
    for (int i = 0; i < 4; ++i) {
        mrow[i] = -1e30f; lrow[i] = 0.f;
        #pragma unroll
        for (int j = 0; j < 8; ++j) O[i][j] = 0.f;
    }

    const int r0 = ty << 2;
    const int c0 = tx << 2;
    const int oc = tx << 3;

    int cb0 = qb - (WIN >> 6); if (cb0 < 0) cb0 = 0;

    for (int cb = cb0; cb <= qb; ++cb) {
        __syncthreads();
        const float* Kg = g_k + ((size_t)bh * TT + (cb << 6)) * DD;
        const float* Vg = g_v + ((size_t)bh * TT + (cb << 6)) * DD;
        #pragma unroll
        for (int i = tid; i < 64 * 32; i += 256) {
            const int r  = i >> 5;
            const int c4 = (i & 31) << 2;
            float4 kv4 = *(const float4*)(Kg + r * DD + c4);
            KsT[(c4 + 0) * 68 + r] = kv4.x;
            KsT[(c4 + 1) * 68 + r] = kv4.y;
            KsT[(c4 + 2) * 68 + r] = kv4.z;
            KsT[(c4 + 3) * 68 + r] = kv4.w;
            ((float4*)Vs)[i] = ((const float4*)Vg)[i];
        }
        __syncthreads();

        float s[4][4];
        #pragma unroll
        for (int i = 0; i < 4; ++i)
            #pragma unroll
            for (int j = 0; j < 4; ++j) s[i][j] = 0.f;

        #pragma unroll 4
        for (int kk = 0; kk < 128; kk += 4) {
            float4 qv[4], kv[4];
            #pragma unroll
            for (int i = 0; i < 4; ++i)
                qv[i] = *(const float4*)&Qs[(r0 + i) * 128 + kk];
            #pragma unroll
            for (int u = 0; u < 4; ++u)
                kv[u] = *(const float4*)&KsT[(kk + u) * 68 + c0];
            #pragma unroll
            for (int i = 0; i < 4; ++i) {
                s[i][0] += qv[i].x*kv[0].x + qv[i].y*kv[1].x + qv[i].z*kv[2].x + qv[i].w*kv[3].x;
                s[i][1] += qv[i].x*kv[0].y + qv[i].y*kv[1].y + qv[i].z*kv[2].y + qv[i].w*kv[3].y;
                s[i][2] += qv[i].x*kv[0].z + qv[i].y*kv[1].z + qv[i].z*kv[2].z + qv[i].w*kv[3].z;
                s[i][3] += qv[i].x*kv[0].w + qv[i].y*kv[1].w + qv[i].z*kv[2].w + qv[i].w*kv[3].w;
            }
        }

        const int kbase = cb << 6;
        float corr[4];
        #pragma unroll
        for (int i = 0; i < 4; ++i) {
            const int qi = q0 + r0 + i;
            #pragma unroll
            for (int j = 0; j < 4; ++j) {
                const int kj = kbase + c0 + j;
                const bool keep = (kj <= qi) && (kj + WIN >= qi);
                s[i][j] = keep ? s[i][j] * scale : -1e30f;
            }
            float rm = fmaxf(fmaxf(s[i][0], s[i][1]), fmaxf(s[i][2], s[i][3]));
            rm = fmaxf(rm, __shfl_xor_sync(0xffffffffu, rm, 1, 16));
            rm = fmaxf(rm, __shfl_xor_sync(0xffffffffu, rm, 2, 16));
            rm = fmaxf(rm, __shfl_xor_sync(0xffffffffu, rm, 4, 16));
            rm = fmaxf(rm, __shfl_xor_sync(0xffffffffu, rm, 8, 16));
            const float mnew = fmaxf(mrow[i], rm);
            corr[i] = __expf(mrow[i] - mnew);
            mrow[i] = mnew;
            float rs = 0.f;
            #pragma unroll
            for (int j = 0; j < 4; ++j) {
                const float p = __expf(s[i][j] - mnew);
                Ps[(r0 + i) * 64 + c0 + j] = p;
                rs += p;
            }
            rs += __shfl_xor_sync(0xffffffffu, rs, 1, 16);
            rs += __shfl_xor_sync(0xffffffffu, rs, 2, 16);
            rs += __shfl_xor_sync(0xffffffffu, rs, 4, 16);
            rs += __shfl_xor_sync(0xffffffffu, rs, 8, 16);
            lrow[i] = lrow[i] * corr[i] + rs;
        }
        __syncthreads();

        #pragma unroll
        for (int i = 0; i < 4; ++i)
            #pragma unroll
            for (int j = 0; j < 8; ++j) O[i][j] *= corr[i];

        #pragma unroll 4
        for (int kk = 0; kk < 64; ++kk) {
            float4 v0 = *(const float4*)&Vs[kk * 128 + oc];
            float4 v1 = *(const float4*)&Vs[kk * 128 + oc + 4];
            #pragma unroll
            for (int i = 0; i < 4; ++i) {
                const float p = Ps[(r0 + i) * 64 + kk];
                O[i][0] += p * v0.x; O[i][1] += p * v0.y;
                O[i][2] += p * v0.z; O[i][3] += p * v0.w;
                O[i][4] += p * v1.x; O[i][5] += p * v1.y;
                O[i][6] += p * v1.z; O[i][7] += p * v1.w;
            }
        }
    }

    const int b = bh >> 3, h = bh & 7;
    #pragma unroll
    for (int i = 0; i < 4; ++i) {
        const float inv = 1.0f / lrow[i];
        const int t = q0 + r0 + i;
        float* dst = g_ao + (((size_t)(b * TT + t) * HH) + h) * DD + oc;
        *(float2*)(dst)     = make_float2(O[i][0]*inv, O[i][1]*inv);
        *(float2*)(dst + 2) = make_float2(O[i][2]*inv, O[i][3]*inv);
        *(float2*)(dst + 4) = make_float2(O[i][4]*inv, O[i][5]*inv);
        *(float2*)(dst + 6) = make_float2(O[i][6]*inv, O[i][7]*inv);
    }
}

// ---------------------------------------------------------------------------
extern "C" void kernel_launch(void* const* d_in, const int* in_sizes, int n_in,
                              void* d_out, int out_size) {
    const float* x     = (const float*)d_in[0];   // [2,4096,1024]
    const float* w_qkv = (const float*)d_in[1];   // [3072,1024]
    const float* w_o   = (const float*)d_in[2];   // [1024,1024]
    float* out = (float*)d_out;                   // [2,4096,1024]

    cudaFuncSetAttribute(attn_kernel,
                         cudaFuncAttributeMaxDynamicSharedMemorySize,
                         ATTN_SMEM_BYTES);

    __nv_bfloat16 *p_xh, *p_xl, *p_wqh, *p_wql, *p_woh, *p_wol, *p_aoh, *p_aol;
    float* p_ao;
    cudaGetSymbolAddress((void**)&p_xh,  g_xh);
    cudaGetSymbolAddress((void**)&p_xl,  g_xl);
    cudaGetSymbolAddress((void**)&p_wqh, g_wqh);
    cudaGetSymbolAddress((void**)&p_wql, g_wql);
    cudaGetSymbolAddress((void**)&p_woh, g_woh);
    cudaGetSymbolAddress((void**)&p_wol, g_wol);
    cudaGetSymbolAddress((void**)&p_aoh, g_aoh);
    cudaGetSymbolAddress((void**)&p_aol, g_aol);
    cudaGetSymbolAddress((void**)&p_ao,  g_ao);

    // split inputs into bf16 hi/lo
    split_bf16<<<(MM*CC/4 + 255)/256, 256>>>(x,     p_xh,  p_xl,  MM*CC/4);
    split_bf16<<<(N3C*CC/4 + 255)/256, 256>>>(w_qkv, p_wqh, p_wql, N3C*CC/4);
    split_bf16<<<(CC*CC/4 + 255)/256, 256>>>(w_o,   p_woh, p_wol, CC*CC/4);

    gemm_bf16<0><<<dim3(N3C/128, MM/128), 256>>>(nullptr);
    rope_kernel<<<(BB * HH * TT * 64) / 256, 256>>>();
    attn_kernel<<<dim3(TT/64, BB*HH), 256, ATTN_SMEM_BYTES>>>();

    split_bf16<<<(MM*CC/4 + 255)/256, 256>>>(p_ao, p_aoh, p_aol, MM*CC/4);
    gemm_bf16<1><<<dim3(CC/128, MM/128), 256>>>(out);
}

// round 12
// speedup vs baseline: 1.5806x; 1.0790x over previous
#include <cuda_runtime.h>
#include <cuda_bf16.h>
#include <cstdint>
#include <math.h>

// Problem constants
#define BB   2
#define TT   4096
#define CC   1024
#define HH   8
#define DD   128
#define WIN  512
#define MM   (BB*TT)          // 8192 rows
#define N3C  (3*CC)           // 3072

// ---------------------------------------------------------------------------
// Scratch (device globals: allocation-free per harness rules)
// ---------------------------------------------------------------------------
__device__ float g_q [BB*HH*TT*DD];   // [bh][t][d]
__device__ float g_k [BB*HH*TT*DD];   // [bh][t][d]
__device__ float g_v [BB*HH*TT*DD];   // [bh][t][d]
__device__ float g_ao[BB*TT*HH*DD];   // [b][t][h][d]  == [M][C] row-major

// bf16 hi/lo split operands for tensor-core GEMMs
__device__ __nv_bfloat16 g_xh [MM*CC],  g_xl [MM*CC];
__device__ __nv_bfloat16 g_wqh[N3C*CC], g_wql[N3C*CC];
__device__ __nv_bfloat16 g_woh[CC*CC],  g_wol[CC*CC];
__device__ __nv_bfloat16 g_aoh[MM*CC],  g_aol[MM*CC];

// ---------------------------------------------------------------------------
// fp32 -> (bf16 hi, bf16 lo) split.  x ~= hi + lo, |residual| ~ 2^-17 |x|
// ---------------------------------------------------------------------------
__global__ __launch_bounds__(256)
void split_bf16(const float* __restrict__ src,
                __nv_bfloat16* __restrict__ hi,
                __nv_bfloat16* __restrict__ lo, int n4) {
    const int i = blockIdx.x * blockDim.x + threadIdx.x;
    if (i >= n4) return;
    float4 v = ((const float4*)src)[i];
    __nv_bfloat16 h0 = __float2bfloat16_rn(v.x);
    __nv_bfloat16 h1 = __float2bfloat16_rn(v.y);
    __nv_bfloat16 h2 = __float2bfloat16_rn(v.z);
    __nv_bfloat16 h3 = __float2bfloat16_rn(v.w);
    __nv_bfloat16 l0 = __float2bfloat16_rn(v.x - __bfloat162float(h0));
    __nv_bfloat16 l1 = __float2bfloat16_rn(v.y - __bfloat162float(h1));
    __nv_bfloat16 l2 = __float2bfloat16_rn(v.z - __bfloat162float(h2));
    __nv_bfloat16 l3 = __float2bfloat16_rn(v.w - __bfloat162float(h3));
    union { __nv_bfloat16 b[4]; uint2 u; } H, L;
    H.b[0]=h0; H.b[1]=h1; H.b[2]=h2; H.b[3]=h3;
    L.b[0]=l0; L.b[1]=l1; L.b[2]=l2; L.b[3]=l3;
    ((uint2*)hi)[i] = H.u;
    ((uint2*)lo)[i] = L.u;
}

// ---------------------------------------------------------------------------
// Tensor-core GEMM: C = A @ W^T with fp32 accuracy via 3-term bf16 split.
// Block tile 128x128, BK=32. 512 threads (16 warps as 4x4), warp tile 32x32.
// cp.async 2-stage double-buffered smem pipeline. mma.sync.m16n8k16 bf16.
// EPI=0: qkv scatter to g_q/g_k/g_v (N=3072).  EPI=1: plain store (N=1024).
// ---------------------------------------------------------------------------
#define SROW 40                   // padded smem row stride in bf16 (conflict-free)
#define ARR  (128*SROW)           // one operand tile in bf16 elems
#define STAGE (4*ARR)             // 4 operand tiles per stage
#define GEMM_SMEM_BYTES (2*STAGE*2)   // 2 stages * bytes   (= 81920)

#define MMA16816(d, a, b0_, b1_)                                          \
    asm volatile("mma.sync.aligned.m16n8k16.row.col.f32.bf16.bf16.f32 "   \
        "{%0,%1,%2,%3}, {%4,%5,%6,%7}, {%8,%9}, {%0,%1,%2,%3};"           \
        : "+f"(d[0]), "+f"(d[1]), "+f"(d[2]), "+f"(d[3])                  \
        : "r"(a[0]), "r"(a[1]), "r"(a[2]), "r"(a[3]), "r"(b0_), "r"(b1_))

#define SMU32(arr, r, c) (*reinterpret_cast<const unsigned*>(&(arr)[(r)*SROW + (c)]))

__device__ __forceinline__ void cpa16(void* smem, const void* g) {
    unsigned s = (unsigned)__cvta_generic_to_shared(smem);
    asm volatile("cp.async.ca.shared.global [%0], [%1], 16;" :: "r"(s), "l"(g));
}
#define CP_COMMIT() asm volatile("cp.async.commit_group;")

template<int EPI>
__global__ __launch_bounds__(512, 1)
void gemm_bf16(float* __restrict__ Out) {
    extern __shared__ __nv_bfloat16 dynsm[];

    const __nv_bfloat16* __restrict__ Ah = (EPI == 0) ? g_xh  : g_aoh;
    const __nv_bfloat16* __restrict__ Al = (EPI == 0) ? g_xl  : g_aol;
    const __nv_bfloat16* __restrict__ Bh = (EPI == 0) ? g_wqh : g_woh;
    const __nv_bfloat16* __restrict__ Bl = (EPI == 0) ? g_wql : g_wol;

    const int bx = blockIdx.x;              // N tile
    const int by = blockIdx.y;              // M tile
    const int tid = threadIdx.x;
    const int warp = tid >> 5, lane = tid & 31;
    const int wm = warp >> 2, wn = warp & 3;        // 4 x 4 warp grid
    const int group = lane >> 2, tg = lane & 3;

    float acc[2][4][4];
    #pragma unroll
    for (int mt = 0; mt < 2; ++mt)
        #pragma unroll
        for (int nt = 0; nt < 4; ++nt)
            #pragma unroll
            for (int e = 0; e < 4; ++e) acc[mt][nt][e] = 0.f;

    const size_t arow = (size_t)by * 128 * 1024;
    const size_t brow = (size_t)bx * 128 * 1024;

    // per-thread load slot: one 16B chunk per operand tile per stage
    const int lr = tid >> 2;                // row 0..127
    const int lk = (tid & 3) << 3;          // col 0,8,16,24
    const int soff = lr * SROW + lk;

    // ---- prologue: stage 0 ----
    {
        const size_t ga = arow + (size_t)lr * 1024 + 0 + lk;
        const size_t gb = brow + (size_t)lr * 1024 + 0 + lk;
        __nv_bfloat16* st = dynsm;
        cpa16(st + 0*ARR + soff, Ah + ga);
        cpa16(st + 1*ARR + soff, Al + ga);
        cpa16(st + 2*ARR + soff, Bh + gb);
        cpa16(st + 3*ARR + soff, Bl + gb);
        CP_COMMIT();
    }

    const int NT = 1024 / 32;   // 32 k-tiles
    for (int i = 0; i < NT; ++i) {
        if (i + 1 < NT) {
            const int k0 = (i + 1) * 32;
            const size_t ga = arow + (size_t)lr * 1024 + k0 + lk;
            const size_t gb = brow + (size_t)lr * 1024 + k0 + lk;
            __nv_bfloat16* st = dynsm + ((i + 1) & 1) * STAGE;
            cpa16(st + 0*ARR + soff, Ah + ga);
            cpa16(st + 1*ARR + soff, Al + ga);
            cpa16(st + 2*ARR + soff, Bh + gb);
            cpa16(st + 3*ARR + soff, Bl + gb);
            CP_COMMIT();
            asm volatile("cp.async.wait_group 1;");
        } else {
            asm volatile("cp.async.wait_group 0;");
        }
        __syncthreads();

        const __nv_bfloat16* st  = dynsm + (i & 1) * STAGE;
        const __nv_bfloat16* sAh = st + 0*ARR;
        const __nv_bfloat16* sAl = st + 1*ARR;
        const __nv_bfloat16* sBh = st + 2*ARR;
        const __nv_bfloat16* sBl = st + 3*ARR;

        #pragma unroll
        for (int ks = 0; ks < 32; ks += 16) {
            const int c = ks + 2*tg;
            unsigned fah[2][4], fal[2][4];
            #pragma unroll
            for (int mt = 0; mt < 2; ++mt) {
                const int r = wm*32 + mt*16 + group;
                fah[mt][0] = SMU32(sAh, r,     c);
                fah[mt][1] = SMU32(sAh, r + 8, c);
                fah[mt][2] = SMU32(sAh, r,     c + 8);
                fah[mt][3] = SMU32(sAh, r + 8, c + 8);
                fal[mt][0] = SMU32(sAl, r,     c);
                fal[mt][1] = SMU32(sAl, r + 8, c);
                fal[mt][2] = SMU32(sAl, r,     c + 8);
                fal[mt][3] = SMU32(sAl, r + 8, c + 8);
            }
            #pragma unroll
            for (int nt = 0; nt < 4; ++nt) {
                const int n = wn*32 + nt*8 + group;
                const unsigned bh0 = SMU32(sBh, n, c);
                const unsigned bh1 = SMU32(sBh, n, c + 8);
                const unsigned bl0 = SMU32(sBl, n, c);
                const unsigned bl1 = SMU32(sBl, n, c + 8);
                #pragma unroll
                for (int mt = 0; mt < 2; ++mt) {
                    MMA16816(acc[mt][nt], fah[mt], bh0, bh1);
                    MMA16816(acc[mt][nt], fah[mt], bl0, bl1);
                    MMA16816(acc[mt][nt], fal[mt], bh0, bh1);
                }
            }
        }
        __syncthreads();
    }

    // ---- epilogue ----
    // fragment D: d0,d1 -> (row=group, col=2tg,2tg+1); d2,d3 -> row=group+8
    if (EPI == 0) {
        const int sec = bx >> 3;
        const int h   = bx & 7;
        float* dst = (sec == 0) ? g_q : ((sec == 1) ? g_k : g_v);
        #pragma unroll
        for (int mt = 0; mt < 2; ++mt) {
            const int m = by*128 + wm*32 + mt*16 + group;
            const int b = m >> 12;
            const int t = m & (TT - 1);
            const size_t rbase = ((size_t)(b * HH + h) * TT + t) * DD;
            #pragma unroll
            for (int nt = 0; nt < 4; ++nt) {
                const int d = wn*32 + nt*8 + tg*2;
                *(float2*)&dst[rbase + d] =
                    make_float2(acc[mt][nt][0], acc[mt][nt][1]);
                *(float2*)&dst[rbase + 8*DD + d] =
                    make_float2(acc[mt][nt][2], acc[mt][nt][3]);
            }
        }
    } else {
        #pragma unroll
        for (int mt = 0; mt < 2; ++mt) {
            const int m = by*128 + wm*32 + mt*16 + group;
            #pragma unroll
            for (int nt = 0; nt < 4; ++nt) {
                const int n = bx*128 + wn*32 + nt*8 + tg*2;
                *(float2*)&Out[(size_t)m * CC + n] =
                    make_float2(acc[mt][nt][0], acc[mt][nt][1]);
                *(float2*)&Out[(size_t)(m + 8) * CC + n] =
                    make_float2(acc[mt][nt][2], acc[mt][nt][3]);
            }
        }
    }
}

// ---------------------------------------------------------------------------
// RoPE in-place on g_q, g_k. One thread per (bh, t, dim-pair i).
// ---------------------------------------------------------------------------
__global__ __launch_bounds__(256)
void rope_kernel() {
    const int idx = blockIdx.x * blockDim.x + threadIdx.x;   // < BB*HH*TT*64
    const int i  = idx & 63;
    const int t  = (idx >> 6) & (TT - 1);
    const int bh = idx >> 18;
    if (bh >= BB * HH) return;

    const float inv_freq = 1.0f / powf(10000.0f, (float)(2 * i) / 128.0f);
    float s, c;
    sincosf((float)t * inv_freq, &s, &c);

    const size_t base = ((size_t)bh * TT + t) * DD;
    float q0 = g_q[base + i], q1 = g_q[base + i + 64];
    g_q[base + i]      = q0 * c - q1 * s;
    g_q[base + i + 64] = q1 * c + q0 * s;
    float k0 = g_k[base + i], k1 = g_k[base + i + 64];
    g_k[base + i]      = k0 * c - k1 * s;
    g_k[base + i + 64] = k1 * c + k0 * s;
}

// ---------------------------------------------------------------------------
// Sliding-window causal flash attention (unchanged from passing baseline).
// ---------------------------------------------------------------------------
#define ATTN_SMEM_FLOATS (64*128 + 128*68 + 64*128 + 64*64)
#define ATTN_SMEM_BYTES  (ATTN_SMEM_FLOATS * 4)

__global__ __launch_bounds__(256)
void attn_kernel() {
    extern __shared__ float sm[];
    float* Qs  = sm;                    // [64][128]
    float* KsT = Qs + 64 * 128;         // [128][68]
    float* Vs  = KsT + 128 * 68;        // [64][128]
    float* Ps  = Vs + 64 * 128;         // [64][64]

    const int qb = blockIdx.x;          // 0..63
    const int bh = blockIdx.y;          // 0..15
    const int q0 = qb << 6;
    const int tid = threadIdx.x;
    const int tx = tid & 15, ty = tid >> 4;
    const float scale = 0.08838834764831845f;   // 1/sqrt(128)

    const float* Qg = g_q + ((size_t)bh * TT + q0) * DD;
    for (int i = tid; i < 64 * 128 / 4; i += 256)
        ((float4*)Qs)[i] = ((const float4*)Qg)[i];

    float mrow[4], lrow[4], O[4][8];
    #pragma unroll
    for (int i = 0; i < 4; ++i) {
        mrow[i] = -1e30f; lrow[i] = 0.f;
        #pragma unroll
        for (int j = 0; j < 8; ++j) O[i][j] = 0.f;
    }

    const int r0 = ty << 2;
    const int c0 = tx << 2;
    const int oc = tx << 3;

    int cb0 = qb - (WIN >> 6); if (cb0 < 0) cb0 = 0;

    for (int cb = cb0; cb <= qb; ++cb) {
        __syncthreads();
        const float* Kg = g_k + ((size_t)bh * TT + (cb << 6)) * DD;
        const float* Vg = g_v + ((size_t)bh * TT + (cb << 6)) * DD;
        #pragma unroll
        for (int i = tid; i < 64 * 32; i += 256) {
            const int r  = i >> 5;
            const int c4 = (i & 31) << 2;
            float4 kv4 = *(const float4*)(Kg + r * DD + c4);
            KsT[(c4 + 0) * 68 + r] = kv4.x;
            KsT[(c4 + 1) * 68 + r] = kv4.y;
            KsT[(c4 + 2) * 68 + r] = kv4.z;
            KsT[(c4 + 3) * 68 + r] = kv4.w;
            ((float4*)Vs)[i] = ((const float4*)Vg)[i];
        }
        __syncthreads();

        float s[4][4];
        #pragma unroll
        for (int i = 0; i < 4; ++i)
            #pragma unroll
            for (int j = 0; j < 4; ++j) s[i][j] = 0.f;

        #pragma unroll 4
        for (int kk = 0; kk < 128; kk += 4) {
            float4 qv[4], kv[4];
            #pragma unroll
            for (int i = 0; i < 4; ++i)
                qv[i] = *(const float4*)&Qs[(r0 + i) * 128 + kk];
            #pragma unroll
            for (int u = 0; u < 4; ++u)
                kv[u] = *(const float4*)&KsT[(kk + u) * 68 + c0];
            #pragma unroll
            for (int i = 0; i < 4; ++i) {
                s[i][0] += qv[i].x*kv[0].x + qv[i].y*kv[1].x + qv[i].z*kv[2].x + qv[i].w*kv[3].x;
                s[i][1] += qv[i].x*kv[0].y + qv[i].y*kv[1].y + qv[i].z*kv[2].y + qv[i].w*kv[3].y;
                s[i][2] += qv[i].x*kv[0].z + qv[i].y*kv[1].z + qv[i].z*kv[2].z + qv[i].w*kv[3].z;
                s[i][3] += qv[i].x*kv[0].w + qv[i].y*kv[1].w + qv[i].z*kv[2].w + qv[i].w*kv[3].w;
            }
        }

        const int kbase = cb << 6;
        float corr[4];
        #pragma unroll
        for (int i = 0; i < 4; ++i) {
            const int qi = q0 + r0 + i;
            #pragma unroll
            for (int j = 0; j < 4; ++j) {
                const int kj = kbase + c0 + j;
                const bool keep = (kj <= qi) && (kj + WIN >= qi);
                s[i][j] = keep ? s[i][j] * scale : -1e30f;
            }
            float rm = fmaxf(fmaxf(s[i][0], s[i][1]), fmaxf(s[i][2], s[i][3]));
            rm = fmaxf(rm, __shfl_xor_sync(0xffffffffu, rm, 1, 16));
            rm = fmaxf(rm, __shfl_xor_sync(0xffffffffu, rm, 2, 16));
            rm = fmaxf(rm, __shfl_xor_sync(0xffffffffu, rm, 4, 16));
            rm = fmaxf(rm, __shfl_xor_sync(0xffffffffu, rm, 8, 16));
            const float mnew = fmaxf(mrow[i], rm);
            corr[i] = __expf(mrow[i] - mnew);
            mrow[i] = mnew;
            float rs = 0.f;
            #pragma unroll
            for (int j = 0; j < 4; ++j) {
                const float p = __expf(s[i][j] - mnew);
                Ps[(r0 + i) * 64 + c0 + j] = p;
                rs += p;
            }
            rs += __shfl_xor_sync(0xffffffffu, rs, 1, 16);
            rs += __shfl_xor_sync(0xffffffffu, rs, 2, 16);
            rs += __shfl_xor_sync(0xffffffffu, rs, 4, 16);
            rs += __shfl_xor_sync(0xffffffffu, rs, 8, 16);
            lrow[i] = lrow[i] * corr[i] + rs;
        }
        __syncthreads();

        #pragma unroll
        for (int i = 0; i < 4; ++i)
            #pragma unroll
            for (int j = 0; j < 8; ++j) O[i][j] *= corr[i];

        #pragma unroll 4
        for (int kk = 0; kk < 64; ++kk) {
            float4 v0 = *(const float4*)&Vs[kk * 128 + oc];
            float4 v1 = *(const float4*)&Vs[kk * 128 + oc + 4];
            #pragma unroll
            for (int i = 0; i < 4; ++i) {
                const float p = Ps[(r0 + i) * 64 + kk];
                O[i][0] += p * v0.x; O[i][1] += p * v0.y;
                O[i][2] += p * v0.z; O[i][3] += p * v0.w;
                O[i][4] += p * v1.x; O[i][5] += p * v1.y;
                O[i][6] += p * v1.z; O[i][7] += p * v1.w;
            }
        }
    }

    const int b = bh >> 3, h = bh & 7;
    #pragma unroll
    for (int i = 0; i < 4; ++i) {
        const float inv = 1.0f / lrow[i];
        const int t = q0 + r0 + i;
        float* dst = g_ao + (((size_t)(b * TT + t) * HH) + h) * DD + oc;
        *(float2*)(dst)     = make_float2(O[i][0]*inv, O[i][1]*inv);
        *(float2*)(dst + 2) = make_float2(O[i][2]*inv, O[i][3]*inv);
        *(float2*)(dst + 4) = make_float2(O[i][4]*inv, O[i][5]*inv);
        *(float2*)(dst + 6) = make_float2(O[i][6]*inv, O[i][7]*inv);
    }
}

// ---------------------------------------------------------------------------
extern "C" void kernel_launch(void* const* d_in, const int* in_sizes, int n_in,
                              void* d_out, int out_size) {
    const float* x     = (const float*)d_in[0];   // [2,4096,1024]
    const float* w_qkv = (const float*)d_in[1];   // [3072,1024]
    const float* w_o   = (const float*)d_in[2];   // [1024,1024]
    float* out = (float*)d_out;                   // [2,4096,1024]

    cudaFuncSetAttribute(attn_kernel,
                         cudaFuncAttributeMaxDynamicSharedMemorySize,
                         ATTN_SMEM_BYTES);
    cudaFuncSetAttribute(gemm_bf16<0>,
                         cudaFuncAttributeMaxDynamicSharedMemorySize,
                         GEMM_SMEM_BYTES);
    cudaFuncSetAttribute(gemm_bf16<1>,
                         cudaFuncAttributeMaxDynamicSharedMemorySize,
                         GEMM_SMEM_BYTES);

    __nv_bfloat16 *p_xh, *p_xl, *p_wqh, *p_wql, *p_woh, *p_wol, *p_aoh, *p_aol;
    float* p_ao;
    cudaGetSymbolAddress((void**)&p_xh,  g_xh);
    cudaGetSymbolAddress((void**)&p_xl,  g_xl);
    cudaGetSymbolAddress((void**)&p_wqh, g_wqh);
    cudaGetSymbolAddress((void**)&p_wql, g_wql);
    cudaGetSymbolAddress((void**)&p_woh, g_woh);
    cudaGetSymbolAddress((void**)&p_wol, g_wol);
    cudaGetSymbolAddress((void**)&p_aoh, g_aoh);
    cudaGetSymbolAddress((void**)&p_aol, g_aol);
    cudaGetSymbolAddress((void**)&p_ao,  g_ao);

    // split inputs into bf16 hi/lo
    split_bf16<<<(MM*CC/4 + 255)/256, 256>>>(x,     p_xh,  p_xl,  MM*CC/4);
    split_bf16<<<(N3C*CC/4 + 255)/256, 256>>>(w_qkv, p_wqh, p_wql, N3C*CC/4);
    split_bf16<<<(CC*CC/4 + 255)/256, 256>>>(w_o,   p_woh, p_wol, CC*CC/4);

    gemm_bf16<0><<<dim3(N3C/128, MM/128), 512, GEMM_SMEM_BYTES>>>(nullptr);
    rope_kernel<<<(BB * HH * TT * 64) / 256, 256>>>();
    attn_kernel<<<dim3(TT/64, BB*HH), 256, ATTN_SMEM_BYTES>>>();

    split_bf16<<<(MM*CC/4 + 255)/256, 256>>>(p_ao, p_aoh, p_aol, MM*CC/4);
    gemm_bf16<1><<<dim3(CC/128, MM/128), 512, GEMM_SMEM_BYTES>>>(out);
}

// round 13
// speedup vs baseline: 1.5932x; 1.0080x over previous
#include <cuda_runtime.h>
#include <cuda_bf16.h>
#include <cstdint>
#include <math.h>

// Problem constants
#define BB   2
#define TT   4096
#define CC   1024
#define HH   8
#define DD   128
#define WIN  512
#define MM   (BB*TT)          // 8192 rows
#define N3C  (3*CC)           // 3072

// ---------------------------------------------------------------------------
// Scratch (device globals: allocation-free per harness rules)
// ---------------------------------------------------------------------------
__device__ float g_q [BB*HH*TT*DD];   // [bh][t][d]
__device__ float g_k [BB*HH*TT*DD];   // [bh][t][d]
__device__ float g_v [BB*HH*TT*DD];   // [bh][t][d]
__device__ float g_ao[BB*TT*HH*DD];   // [b][t][h][d]  == [M][C] row-major

// bf16 hi/lo split operands for tensor-core GEMMs
__device__ __nv_bfloat16 g_xh [MM*CC],  g_xl [MM*CC];
__device__ __nv_bfloat16 g_wqh[N3C*CC], g_wql[N3C*CC];
__device__ __nv_bfloat16 g_woh[CC*CC],  g_wol[CC*CC];
__device__ __nv_bfloat16 g_aoh[MM*CC],  g_aol[MM*CC];

// ---------------------------------------------------------------------------
// fp32 -> (bf16 hi, bf16 lo) split.  x ~= hi + lo, |residual| ~ 2^-17 |x|
// ---------------------------------------------------------------------------
__global__ __launch_bounds__(256)
void split_bf16(const float* __restrict__ src,
                __nv_bfloat16* __restrict__ hi,
                __nv_bfloat16* __restrict__ lo, int n4) {
    const int i = blockIdx.x * blockDim.x + threadIdx.x;
    if (i >= n4) return;
    float4 v = ((const float4*)src)[i];
    __nv_bfloat16 h0 = __float2bfloat16_rn(v.x);
    __nv_bfloat16 h1 = __float2bfloat16_rn(v.y);
    __nv_bfloat16 h2 = __float2bfloat16_rn(v.z);
    __nv_bfloat16 h3 = __float2bfloat16_rn(v.w);
    __nv_bfloat16 l0 = __float2bfloat16_rn(v.x - __bfloat162float(h0));
    __nv_bfloat16 l1 = __float2bfloat16_rn(v.y - __bfloat162float(h1));
    __nv_bfloat16 l2 = __float2bfloat16_rn(v.z - __bfloat162float(h2));
    __nv_bfloat16 l3 = __float2bfloat16_rn(v.w - __bfloat162float(h3));
    union { __nv_bfloat16 b[4]; uint2 u; } H, L;
    H.b[0]=h0; H.b[1]=h1; H.b[2]=h2; H.b[3]=h3;
    L.b[0]=l0; L.b[1]=l1; L.b[2]=l2; L.b[3]=l3;
    ((uint2*)hi)[i] = H.u;
    ((uint2*)lo)[i] = L.u;
}

// ---------------------------------------------------------------------------
// Tensor-core GEMM: C = A @ W^T with fp32 accuracy via 3-term bf16 split.
// Block tile 128x128, BK=32. 512 threads (16 warps as 4x4), warp tile 32x32.
// 3-stage cp.async pipeline + ldmatrix.x4 fragment loads.
// EPI=0: qkv scatter to g_q/g_k/g_v (N=3072).  EPI=1: plain store (N=1024).
// ---------------------------------------------------------------------------
#define SROW 40                   // padded smem row stride in bf16 (conflict-free)
#define ARR  (128*SROW)           // one operand tile in bf16 elems
#define STAGE (4*ARR)             // 4 operand tiles per stage
#define NSTAGE 3
#define GEMM_SMEM_BYTES (NSTAGE*STAGE*2)   // 122880 bytes

#define MMA16816(d, a, b0_, b1_)                                          \
    asm volatile("mma.sync.aligned.m16n8k16.row.col.f32.bf16.bf16.f32 "   \
        "{%0,%1,%2,%3}, {%4,%5,%6,%7}, {%8,%9}, {%0,%1,%2,%3};"           \
        : "+f"(d[0]), "+f"(d[1]), "+f"(d[2]), "+f"(d[3])                  \
        : "r"(a[0]), "r"(a[1]), "r"(a[2]), "r"(a[3]), "r"(b0_), "r"(b1_))

#define LDSM4(R, addr)                                                    \
    asm volatile("ldmatrix.sync.aligned.m8n8.x4.shared.b16 "              \
        "{%0,%1,%2,%3}, [%4];"                                            \
        : "=r"((R)[0]), "=r"((R)[1]), "=r"((R)[2]), "=r"((R)[3])          \
        : "r"(addr))

__device__ __forceinline__ void cpa16(void* smem, const void* g) {
    unsigned s = (unsigned)__cvta_generic_to_shared(smem);
    asm volatile("cp.async.ca.shared.global [%0], [%1], 16;" :: "r"(s), "l"(g));
}
#define CP_COMMIT() asm volatile("cp.async.commit_group;")

template<int EPI>
__global__ __launch_bounds__(512, 1)
void gemm_bf16(float* __restrict__ Out) {
    extern __shared__ __nv_bfloat16 dynsm[];

    const __nv_bfloat16* __restrict__ Ah = (EPI == 0) ? g_xh  : g_aoh;
    const __nv_bfloat16* __restrict__ Al = (EPI == 0) ? g_xl  : g_aol;
    const __nv_bfloat16* __restrict__ Bh = (EPI == 0) ? g_wqh : g_woh;
    const __nv_bfloat16* __restrict__ Bl = (EPI == 0) ? g_wql : g_wol;

    const int bx = blockIdx.x;              // N tile
    const int by = blockIdx.y;              // M tile
    const int tid = threadIdx.x;
    const int warp = tid >> 5, lane = tid & 31;
    const int wm = warp >> 2, wn = warp & 3;        // 4 x 4 warp grid
    const int group = lane >> 2, tg = lane & 3;

    float acc[2][4][4];
    #pragma unroll
    for (int mt = 0; mt < 2; ++mt)
        #pragma unroll
        for (int nt = 0; nt < 4; ++nt)
            #pragma unroll
            for (int e = 0; e < 4; ++e) acc[mt][nt][e] = 0.f;

    const size_t arow = (size_t)by * 128 * 1024;
    const size_t brow = (size_t)bx * 128 * 1024;

    // per-thread cp.async slot: one 16B chunk per operand tile per stage
    const int lr = tid >> 2;                // row 0..127
    const int lk = (tid & 3) << 3;          // col 0,8,16,24
    const int soff = lr * SROW + lk;

    // per-thread ldmatrix source geometry (within a 16-row / 16-col block)
    const unsigned smem_u32 = (unsigned)__cvta_generic_to_shared(dynsm);
    const int lq = lane & 7, lseg = lane >> 3;
    // A: m0=(r+0,c+0) m1=(r+8,c+0) m2=(r+0,c+8) m3=(r+8,c+8)
    const int aRow = lq + (lseg & 1) * 8;
    const int aCol = (lseg >> 1) * 8;
    // B: m0=(n+0,k+0) m1=(n+0,k+8) m2=(n+8,k+0) m3=(n+8,k+8)
    const int bRow = lq + (lseg >> 1) * 8;
    const int bCol = (lseg & 1) * 8;

    const int aOff0 = (wm * 32 + aRow) * SROW + aCol;   // + mt*16*SROW + ks
    const int bOff0 = (wn * 32 + bRow) * SROW + bCol;   // + p *16*SROW + ks

    const int NT = 1024 / 32;   // 32 k-tiles

    // ---- prologue: stages 0 and 1 ----
    #pragma unroll
    for (int s = 0; s < 2; ++s) {
        const int k0 = s * 32;
        const size_t ga = arow + (size_t)lr * 1024 + k0 + lk;
        const size_t gb = brow + (size_t)lr * 1024 + k0 + lk;
        __nv_bfloat16* st = dynsm + s * STAGE;
        cpa16(st + 0*ARR + soff, Ah + ga);
        cpa16(st + 1*ARR + soff, Al + ga);
        cpa16(st + 2*ARR + soff, Bh + gb);
        cpa16(st + 3*ARR + soff, Bl + gb);
        CP_COMMIT();
    }

    for (int i = 0; i < NT; ++i) {
        if (i + 2 < NT) {
            const int k0 = (i + 2) * 32;
            const size_t ga = arow + (size_t)lr * 1024 + k0 + lk;
            const size_t gb = brow + (size_t)lr * 1024 + k0 + lk;
            __nv_bfloat16* st = dynsm + ((i + 2) % NSTAGE) * STAGE;
            cpa16(st + 0*ARR + soff, Ah + ga);
            cpa16(st + 1*ARR + soff, Al + ga);
            cpa16(st + 2*ARR + soff, Bh + gb);
            cpa16(st + 3*ARR + soff, Bl + gb);
        }
        CP_COMMIT();                      // (possibly empty) group each iter
        asm volatile("cp.async.wait_group 2;");
        __syncthreads();

        const unsigned stB = smem_u32 + 2u * (unsigned)((i % NSTAGE) * STAGE);
        const unsigned aH = stB;                    // sAh
        const unsigned aL = stB + 2u*ARR;           // sAl
        const unsigned bH = stB + 4u*ARR;           // sBh
        const unsigned bL = stB + 6u*ARR;           // sBl

        #pragma unroll
        for (int ks = 0; ks < 32; ks += 16) {
            unsigned fah[2][4], fal[2][4];
            #pragma unroll
            for (int mt = 0; mt < 2; ++mt) {
                const unsigned off = 2u * (unsigned)(aOff0 + mt*16*SROW + ks);
                LDSM4(fah[mt], aH + off);
                LDSM4(fal[mt], aL + off);
            }
            #pragma unroll
            for (int p = 0; p < 2; ++p) {
                unsigned bh4[4], bl4[4];
                const unsigned off = 2u * (unsigned)(bOff0 + p*16*SROW + ks);
                LDSM4(bh4, bH + off);
                LDSM4(bl4, bL + off);
                #pragma unroll
                for (int sub = 0; sub < 2; ++sub) {
                    const int nt = p*2 + sub;
                    const unsigned bh0 = bh4[2*sub], bh1 = bh4[2*sub+1];
                    const unsigned bl0 = bl4[2*sub], bl1 = bl4[2*sub+1];
                    #pragma unroll
                    for (int mt = 0; mt < 2; ++mt) {
                        MMA16816(acc[mt][nt], fah[mt], bh0, bh1);
                        MMA16816(acc[mt][nt], fah[mt], bl0, bl1);
                        MMA16816(acc[mt][nt], fal[mt], bh0, bh1);
                    }
                }
            }
        }
        __syncthreads();
    }

    // ---- epilogue ----
    // fragment D: d0,d1 -> (row=group, col=2tg,2tg+1); d2,d3 -> row=group+8
    if (EPI == 0) {
        const int sec = bx >> 3;
        const int h   = bx & 7;
        float* dst = (sec == 0) ? g_q : ((sec == 1) ? g_k : g_v);
        #pragma unroll
        for (int mt = 0; mt < 2; ++mt) {
            const int m = by*128 + wm*32 + mt*16 + group;
            const int b = m >> 12;
            const int t = m & (TT - 1);
            const size_t rbase = ((size_t)(b * HH + h) * TT + t) * DD;
            #pragma unroll
            for (int nt = 0; nt < 4; ++nt) {
                const int d = wn*32 + nt*8 + tg*2;
                *(float2*)&dst[rbase + d] =
                    make_float2(acc[mt][nt][0], acc[mt][nt][1]);
                *(float2*)&dst[rbase + 8*DD + d] =
                    make_float2(acc[mt][nt][2], acc[mt][nt][3]);
            }
        }
    } else {
        #pragma unroll
        for (int mt = 0; mt < 2; ++mt) {
            const int m = by*128 + wm*32 + mt*16 + group;
            #pragma unroll
            for (int nt = 0; nt < 4; ++nt) {
                const int n = bx*128 + wn*32 + nt*8 + tg*2;
                *(float2*)&Out[(size_t)m * CC + n] =
                    make_float2(acc[mt][nt][0], acc[mt][nt][1]);
                *(float2*)&Out[(size_t)(m + 8) * CC + n] =
                    make_float2(acc[mt][nt][2], acc[mt][nt][3]);
            }
        }
    }
}

// ---------------------------------------------------------------------------
// RoPE in-place on g_q, g_k. One thread per (bh, t, dim-pair i).
// ---------------------------------------------------------------------------
__global__ __launch_bounds__(256)
void rope_kernel() {
    const int idx = blockIdx.x * blockDim.x + threadIdx.x;   // < BB*HH*TT*64
    const int i  = idx & 63;
    const int t  = (idx >> 6) & (TT - 1);
    const int bh = idx >> 18;
    if (bh >= BB * HH) return;

    const float inv_freq = 1.0f / powf(10000.0f, (float)(2 * i) / 128.0f);
    float s, c;
    sincosf((float)t * inv_freq, &s, &c);

    const size_t base = ((size_t)bh * TT + t) * DD;
    float q0 = g_q[base + i], q1 = g_q[base + i + 64];
    g_q[base + i]      = q0 * c - q1 * s;
    g_q[base + i + 64] = q1 * c + q0 * s;
    float k0 = g_k[base + i], k1 = g_k[base + i + 64];
    g_k[base + i]      = k0 * c - k1 * s;
    g_k[base + i + 64] = k1 * c + k0 * s;
}

// ---------------------------------------------------------------------------
// Sliding-window causal flash attention (unchanged from passing baseline).
// ---------------------------------------------------------------------------
#define ATTN_SMEM_FLOATS (64*128 + 128*68 + 64*128 + 64*64)
#define ATTN_SMEM_BYTES  (ATTN_SMEM_FLOATS * 4)

__global__ __launch_bounds__(256)
void attn_kernel() {
    extern __shared__ float sm[];
    float* Qs  = sm;                    // [64][128]
    float* KsT = Qs + 64 * 128;         // [128][68]
    float* Vs  = KsT + 128 * 68;        // [64][128]
    float* Ps  = Vs + 64 * 128;         // [64][64]

    const int qb = blockIdx.x;          // 0..63
    const int bh = blockIdx.y;          // 0..15
    const int q0 = qb << 6;
    const int tid = threadIdx.x;
    const int tx = tid & 15, ty = tid >> 4;
    const float scale = 0.08838834764831845f;   // 1/sqrt(128)

    const float* Qg = g_q + ((size_t)bh * TT + q0) * DD;
    for (int i = tid; i < 64 * 128 / 4; i += 256)
        ((float4*)Qs)[i] = ((const float4*)Qg)[i];

    float mrow[4], lrow[4], O[4][8];
    #pragma unroll
    for (int i = 0; i < 4; ++i) {
        mrow[i] = -1e30f; lrow[i] = 0.f;
        #pragma unroll
        for (int j = 0; j < 8; ++j) O[i][j] = 0.f;
    }

    const int r0 = ty << 2;
    const int c0 = tx << 2;
    const int oc = tx << 3;

    int cb0 = qb - (WIN >> 6); if (cb0 < 0) cb0 = 0;

    for (int cb = cb0; cb <= qb; ++cb) {
        __syncthreads();
        const float* Kg = g_k + ((size_t)bh * TT + (cb << 6)) * DD;
        const float* Vg = g_v + ((size_t)bh * TT + (cb << 6)) * DD;
        #pragma unroll
        for (int i = tid; i < 64 * 32; i += 256) {
            const int r  = i >> 5;
            const int c4 = (i & 31) << 2;
            float4 kv4 = *(const float4*)(Kg + r * DD + c4);
            KsT[(c4 + 0) * 68 + r] = kv4.x;
            KsT[(c4 + 1) * 68 + r] = kv4.y;
            KsT[(c4 + 2) * 68 + r] = kv4.z;
            KsT[(c4 + 3) * 68 + r] = kv4.w;
            ((float4*)Vs)[i] = ((const float4*)Vg)[i];
        }
        __syncthreads();

        float s[4][4];
        #pragma unroll
        for (int i = 0; i < 4; ++i)
            #pragma unroll
            for (int j = 0; j < 4; ++j) s[i][j] = 0.f;

        #pragma unroll 4
        for (int kk = 0; kk < 128; kk += 4) {
            float4 qv[4], kv[4];
            #pragma unroll
            for (int i = 0; i < 4; ++i)
                qv[i] = *(const float4*)&Qs[(r0 + i) * 128 + kk];
            #pragma unroll
            for (int u = 0; u < 4; ++u)
                kv[u] = *(const float4*)&KsT[(kk + u) * 68 + c0];
            #pragma unroll
            for (int i = 0; i < 4; ++i) {
                s[i][0] += qv[i].x*kv[0].x + qv[i].y*kv[1].x + qv[i].z*kv[2].x + qv[i].w*kv[3].x;
                s[i][1] += qv[i].x*kv[0].y + qv[i].y*kv[1].y + qv[i].z*kv[2].y + qv[i].w*kv[3].y;
                s[i][2] += qv[i].x*kv[0].z + qv[i].y*kv[1].z + qv[i].z*kv[2].z + qv[i].w*kv[3].z;
                s[i][3] += qv[i].x*kv[0].w + qv[i].y*kv[1].w + qv[i].z*kv[2].w + qv[i].w*kv[3].w;
            }
        }

        const int kbase = cb << 6;
        float corr[4];
        #pragma unroll
        for (int i = 0; i < 4; ++i) {
            const int qi = q0 + r0 + i;
            #pragma unroll
            for (int j = 0; j < 4; ++j) {
                const int kj = kbase + c0 + j;
                const bool keep = (kj <= qi) && (kj + WIN >= qi);
                s[i][j] = keep ? s[i][j] * scale : -1e30f;
            }
            float rm = fmaxf(fmaxf(s[i][0], s[i][1]), fmaxf(s[i][2], s[i][3]));
            rm = fmaxf(rm, __shfl_xor_sync(0xffffffffu, rm, 1, 16));
            rm = fmaxf(rm, __shfl_xor_sync(0xffffffffu, rm, 2, 16));
            rm = fmaxf(rm, __shfl_xor_sync(0xffffffffu, rm, 4, 16));
            rm = fmaxf(rm, __shfl_xor_sync(0xffffffffu, rm, 8, 16));
            const float mnew = fmaxf(mrow[i], rm);
            corr[i] = __expf(mrow[i] - mnew);
            mrow[i] = mnew;
            float rs = 0.f;
            #pragma unroll
            for (int j = 0; j < 4; ++j) {
                const float p = __expf(s[i][j] - mnew);
                Ps[(r0 + i) * 64 + c0 + j] = p;
                rs += p;
            }
            rs += __shfl_xor_sync(0xffffffffu, rs, 1, 16);
            rs += __shfl_xor_sync(0xffffffffu, rs, 2, 16);
            rs += __shfl_xor_sync(0xffffffffu, rs, 4, 16);
            rs += __shfl_xor_sync(0xffffffffu, rs, 8, 16);
            lrow[i] = lrow[i] * corr[i] + rs;
        }
        __syncthreads();

        #pragma unroll
        for (int i = 0; i < 4; ++i)
            #pragma unroll
            for (int j = 0; j < 8; ++j) O[i][j] *= corr[i];

        #pragma unroll 4
        for (int kk = 0; kk < 64; ++kk) {
            float4 v0 = *(const float4*)&Vs[kk * 128 + oc];
            float4 v1 = *(const float4*)&Vs[kk * 128 + oc + 4];
            #pragma unroll
            for (int i = 0; i < 4; ++i) {
                const float p = Ps[(r0 + i) * 64 + kk];
                O[i][0] += p * v0.x; O[i][1] += p * v0.y;
                O[i][2] += p * v0.z; O[i][3] += p * v0.w;
                O[i][4] += p * v1.x; O[i][5] += p * v1.y;
                O[i][6] += p * v1.z; O[i][7] += p * v1.w;
            }
        }
    }

    const int b = bh >> 3, h = bh & 7;
    #pragma unroll
    for (int i = 0; i < 4; ++i) {
        const float inv = 1.0f / lrow[i];
        const int t = q0 + r0 + i;
        float* dst = g_ao + (((size_t)(b * TT + t) * HH) + h) * DD + oc;
        *(float2*)(dst)     = make_float2(O[i][0]*inv, O[i][1]*inv);
        *(float2*)(dst + 2) = make_float2(O[i][2]*inv, O[i][3]*inv);
        *(float2*)(dst + 4) = make_float2(O[i][4]*inv, O[i][5]*inv);
        *(float2*)(dst + 6) = make_float2(O[i][6]*inv, O[i][7]*inv);
    }
}

// ---------------------------------------------------------------------------
extern "C" void kernel_launch(void* const* d_in, const int* in_sizes, int n_in,
                              void* d_out, int out_size) {
    const float* x     = (const float*)d_in[0];   // [2,4096,1024]
    const float* w_qkv = (const float*)d_in[1];   // [3072,1024]
    const float* w_o   = (const float*)d_in[2];   // [1024,1024]
    float* out = (float*)d_out;                   // [2,4096,1024]

    cudaFuncSetAttribute(attn_kernel,
                         cudaFuncAttributeMaxDynamicSharedMemorySize,
                         ATTN_SMEM_BYTES);
    cudaFuncSetAttribute(gemm_bf16<0>,
                         cudaFuncAttributeMaxDynamicSharedMemorySize,
                         GEMM_SMEM_BYTES);
    cudaFuncSetAttribute(gemm_bf16<1>,
                         cudaFuncAttributeMaxDynamicSharedMemorySize,
                         GEMM_SMEM_BYTES);

    __nv_bfloat16 *p_xh, *p_xl, *p_wqh, *p_wql, *p_woh, *p_wol, *p_aoh, *p_aol;
    float* p_ao;
    cudaGetSymbolAddress((void**)&p_xh,  g_xh);
    cudaGetSymbolAddress((void**)&p_xl,  g_xl);
    cudaGetSymbolAddress((void**)&p_wqh, g_wqh);
    cudaGetSymbolAddress((void**)&p_wql, g_wql);
    cudaGetSymbolAddress((void**)&p_woh, g_woh);
    cudaGetSymbolAddress((void**)&p_wol, g_wol);
    cudaGetSymbolAddress((void**)&p_aoh, g_aoh);
    cudaGetSymbolAddress((void**)&p_aol, g_aol);
    cudaGetSymbolAddress((void**)&p_ao,  g_ao);

    // split inputs into bf16 hi/lo
    split_bf16<<<(MM*CC/4 + 255)/256, 256>>>(x,     p_xh,  p_xl,  MM*CC/4);
    split_bf16<<<(N3C*CC/4 + 255)/256, 256>>>(w_qkv, p_wqh, p_wql, N3C*CC/4);
    split_bf16<<<(CC*CC/4 + 255)/256, 256>>>(w_o,   p_woh, p_wol, CC*CC/4);

    gemm_bf16<0><<<dim3(N3C/128, MM/128), 512, GEMM_SMEM_BYTES>>>(nullptr);
    rope_kernel<<<(BB * HH * TT * 64) / 256, 256>>>();
    attn_kernel<<<dim3(TT/64, BB*HH), 256, ATTN_SMEM_BYTES>>>();

    split_bf16<<<(MM*CC/4 + 255)/256, 256>>>(p_ao, p_aoh, p_aol, MM*CC/4);
    gemm_bf16<1><<<dim3(CC/128, MM/128), 512, GEMM_SMEM_BYTES>>>(out);
}

// round 14
// speedup vs baseline: 2.5706x; 1.6135x over previous
#include <cuda_runtime.h>
#include <cuda_bf16.h>
#include <cstdint>
#include <math.h>

// Problem constants
#define BB   2
#define TT   4096
#define CC   1024
#define HH   8
#define DD   128
#define WIN  512
#define MM   (BB*TT)          // 8192 rows
#define N3C  (3*CC)           // 3072

// ---------------------------------------------------------------------------
// Scratch (device globals: allocation-free per harness rules)
// ---------------------------------------------------------------------------
__device__ float g_q [BB*HH*TT*DD];   // [bh][t][d]
__device__ float g_k [BB*HH*TT*DD];   // [bh][t][d]
__device__ float g_v [BB*HH*TT*DD];   // [bh][t][d]
__device__ float g_ao[BB*TT*HH*DD];   // [b][t][h][d]  == [M][C] row-major

// bf16 hi/lo split operands for tensor-core GEMMs
__device__ __nv_bfloat16 g_xh [MM*CC],  g_xl [MM*CC];
__device__ __nv_bfloat16 g_wqh[N3C*CC], g_wql[N3C*CC];
__device__ __nv_bfloat16 g_woh[CC*CC],  g_wol[CC*CC];
__device__ __nv_bfloat16 g_aoh[MM*CC],  g_aol[MM*CC];

// bf16 hi/lo split q/k/v for tensor-core attention (post-RoPE, q pre-scaled)
__device__ __nv_bfloat16 g_qh[BB*HH*TT*DD], g_ql[BB*HH*TT*DD];
__device__ __nv_bfloat16 g_kh[BB*HH*TT*DD], g_kl[BB*HH*TT*DD];
__device__ __nv_bfloat16 g_vh[BB*HH*TT*DD], g_vl[BB*HH*TT*DD];

// ---------------------------------------------------------------------------
// fp32 -> (bf16 hi, bf16 lo) split.  x ~= hi + lo, |residual| ~ 2^-17 |x|
// ---------------------------------------------------------------------------
__global__ __launch_bounds__(256)
void split_bf16(const float* __restrict__ src,
                __nv_bfloat16* __restrict__ hi,
                __nv_bfloat16* __restrict__ lo, int n4) {
    const int i = blockIdx.x * blockDim.x + threadIdx.x;
    if (i >= n4) return;
    float4 v = ((const float4*)src)[i];
    __nv_bfloat16 h0 = __float2bfloat16_rn(v.x);
    __nv_bfloat16 h1 = __float2bfloat16_rn(v.y);
    __nv_bfloat16 h2 = __float2bfloat16_rn(v.z);
    __nv_bfloat16 h3 = __float2bfloat16_rn(v.w);
    __nv_bfloat16 l0 = __float2bfloat16_rn(v.x - __bfloat162float(h0));
    __nv_bfloat16 l1 = __float2bfloat16_rn(v.y - __bfloat162float(h1));
    __nv_bfloat16 l2 = __float2bfloat16_rn(v.z - __bfloat162float(h2));
    __nv_bfloat16 l3 = __float2bfloat16_rn(v.w - __bfloat162float(h3));
    union { __nv_bfloat16 b[4]; uint2 u; } H, L;
    H.b[0]=h0; H.b[1]=h1; H.b[2]=h2; H.b[3]=h3;
    L.b[0]=l0; L.b[1]=l1; L.b[2]=l2; L.b[3]=l3;
    ((uint2*)hi)[i] = H.u;
    ((uint2*)lo)[i] = L.u;
}

// ---------------------------------------------------------------------------
// Tensor-core GEMM (unchanged from round-13 best): 3-stage cp.async + ldmatrix
// ---------------------------------------------------------------------------
#define SROW 40
#define ARR  (128*SROW)
#define STAGE (4*ARR)
#define NSTAGE 3
#define GEMM_SMEM_BYTES (NSTAGE*STAGE*2)

#define MMA16816(d, a, b0_, b1_)                                          \
    asm volatile("mma.sync.aligned.m16n8k16.row.col.f32.bf16.bf16.f32 "   \
        "{%0,%1,%2,%3}, {%4,%5,%6,%7}, {%8,%9}, {%0,%1,%2,%3};"           \
        : "+f"(d[0]), "+f"(d[1]), "+f"(d[2]), "+f"(d[3])                  \
        : "r"(a[0]), "r"(a[1]), "r"(a[2]), "r"(a[3]), "r"(b0_), "r"(b1_))

#define LDSM4(R, addr)                                                    \
    asm volatile("ldmatrix.sync.aligned.m8n8.x4.shared.b16 "              \
        "{%0,%1,%2,%3}, [%4];"                                            \
        : "=r"((R)[0]), "=r"((R)[1]), "=r"((R)[2]), "=r"((R)[3])          \
        : "r"(addr))

#define LDSM4T(R, addr)                                                   \
    asm volatile("ldmatrix.sync.aligned.m8n8.x4.trans.shared.b16 "        \
        "{%0,%1,%2,%3}, [%4];"                                            \
        : "=r"((R)[0]), "=r"((R)[1]), "=r"((R)[2]), "=r"((R)[3])          \
        : "r"(addr))

__device__ __forceinline__ unsigned pack_bf16x2(float lo, float hi) {
    unsigned r;
    asm("cvt.rn.bf16x2.f32 %0, %1, %2;" : "=r"(r) : "f"(hi), "f"(lo));
    return r;
}

__device__ __forceinline__ void cpa16(void* smem, const void* g) {
    unsigned s = (unsigned)__cvta_generic_to_shared(smem);
    asm volatile("cp.async.ca.shared.global [%0], [%1], 16;" :: "r"(s), "l"(g));
}
#define CP_COMMIT() asm volatile("cp.async.commit_group;")
#define SMU32(arr, r, c) (*reinterpret_cast<const unsigned*>(&(arr)[(r)*SROW + (c)]))

template<int EPI>
__global__ __launch_bounds__(512, 1)
void gemm_bf16(float* __restrict__ Out) {
    extern __shared__ __nv_bfloat16 dynsm[];

    const __nv_bfloat16* __restrict__ Ah = (EPI == 0) ? g_xh  : g_aoh;
    const __nv_bfloat16* __restrict__ Al = (EPI == 0) ? g_xl  : g_aol;
    const __nv_bfloat16* __restrict__ Bh = (EPI == 0) ? g_wqh : g_woh;
    const __nv_bfloat16* __restrict__ Bl = (EPI == 0) ? g_wql : g_wol;

    const int bx = blockIdx.x;
    const int by = blockIdx.y;
    const int tid = threadIdx.x;
    const int warp = tid >> 5, lane = tid & 31;
    const int wm = warp >> 2, wn = warp & 3;
    const int group = lane >> 2, tg = lane & 3;

    float acc[2][4][4];
    #pragma unroll
    for (int mt = 0; mt < 2; ++mt)
        #pragma unroll
        for (int nt = 0; nt < 4; ++nt)
            #pragma unroll
            for (int e = 0; e < 4; ++e) acc[mt][nt][e] = 0.f;

    const size_t arow = (size_t)by * 128 * 1024;
    const size_t brow = (size_t)bx * 128 * 1024;

    const int lr = tid >> 2;
    const int lk = (tid & 3) << 3;
    const int soff = lr * SROW + lk;

    const unsigned smem_u32 = (unsigned)__cvta_generic_to_shared(dynsm);
    const int lq = lane & 7, lseg = lane >> 3;
    const int aRow = lq + (lseg & 1) * 8;
    const int aCol = (lseg >> 1) * 8;
    const int bRow = lq + (lseg >> 1) * 8;
    const int bCol = (lseg & 1) * 8;

    const int aOff0 = (wm * 32 + aRow) * SROW + aCol;
    const int bOff0 = (wn * 32 + bRow) * SROW + bCol;

    const int NT = 1024 / 32;

    #pragma unroll
    for (int s = 0; s < 2; ++s) {
        const int k0 = s * 32;
        const size_t ga = arow + (size_t)lr * 1024 + k0 + lk;
        const size_t gb = brow + (size_t)lr * 1024 + k0 + lk;
        __nv_bfloat16* st = dynsm + s * STAGE;
        cpa16(st + 0*ARR + soff, Ah + ga);
        cpa16(st + 1*ARR + soff, Al + ga);
        cpa16(st + 2*ARR + soff, Bh + gb);
        cpa16(st + 3*ARR + soff, Bl + gb);
        CP_COMMIT();
    }

    for (int i = 0; i < NT; ++i) {
        if (i + 2 < NT) {
            const int k0 = (i + 2) * 32;
            const size_t ga = arow + (size_t)lr * 1024 + k0 + lk;
            const size_t gb = brow + (size_t)lr * 1024 + k0 + lk;
            __nv_bfloat16* st = dynsm + ((i + 2) % NSTAGE) * STAGE;
            cpa16(st + 0*ARR + soff, Ah + ga);
            cpa16(st + 1*ARR + soff, Al + ga);
            cpa16(st + 2*ARR + soff, Bh + gb);
            cpa16(st + 3*ARR + soff, Bl + gb);
        }
        CP_COMMIT();
        asm volatile("cp.async.wait_group 2;");
        __syncthreads();

        const unsigned stB = smem_u32 + 2u * (unsigned)((i % NSTAGE) * STAGE);
        const unsigned aH = stB;
        const unsigned aL = stB + 2u*ARR;
        const unsigned bH = stB + 4u*ARR;
        const unsigned bL = stB + 6u*ARR;

        #pragma unroll
        for (int ks = 0; ks < 32; ks += 16) {
            unsigned fah[2][4], fal[2][4];
            #pragma unroll
            for (int mt = 0; mt < 2; ++mt) {
                const unsigned off = 2u * (unsigned)(aOff0 + mt*16*SROW + ks);
                LDSM4(fah[mt], aH + off);
                LDSM4(fal[mt], aL + off);
            }
            #pragma unroll
            for (int p = 0; p < 2; ++p) {
                unsigned bh4[4], bl4[4];
                const unsigned off = 2u * (unsigned)(bOff0 + p*16*SROW + ks);
                LDSM4(bh4, bH + off);
                LDSM4(bl4, bL + off);
                #pragma unroll
                for (int sub = 0; sub < 2; ++sub) {
                    const int nt = p*2 + sub;
                    const unsigned bh0 = bh4[2*sub], bh1 = bh4[2*sub+1];
                    const unsigned bl0 = bl4[2*sub], bl1 = bl4[2*sub+1];
                    #pragma unroll
                    for (int mt = 0; mt < 2; ++mt) {
                        MMA16816(acc[mt][nt], fah[mt], bh0, bh1);
                        MMA16816(acc[mt][nt], fah[mt], bl0, bl1);
                        MMA16816(acc[mt][nt], fal[mt], bh0, bh1);
                    }
                }
            }
        }
        __syncthreads();
    }

    if (EPI == 0) {
        const int sec = bx >> 3;
        const int h   = bx & 7;
        float* dst = (sec == 0) ? g_q : ((sec == 1) ? g_k : g_v);
        #pragma unroll
        for (int mt = 0; mt < 2; ++mt) {
            const int m = by*128 + wm*32 + mt*16 + group;
            const int b = m >> 12;
            const int t = m & (TT - 1);
            const size_t rbase = ((size_t)(b * HH + h) * TT + t) * DD;
            #pragma unroll
            for (int nt = 0; nt < 4; ++nt) {
                const int d = wn*32 + nt*8 + tg*2;
                *(float2*)&dst[rbase + d] =
                    make_float2(acc[mt][nt][0], acc[mt][nt][1]);
                *(float2*)&dst[rbase + 8*DD + d] =
                    make_float2(acc[mt][nt][2], acc[mt][nt][3]);
            }
        }
    } else {
        #pragma unroll
        for (int mt = 0; mt < 2; ++mt) {
            const int m = by*128 + wm*32 + mt*16 + group;
            #pragma unroll
            for (int nt = 0; nt < 4; ++nt) {
                const int n = bx*128 + wn*32 + nt*8 + tg*2;
                *(float2*)&Out[(size_t)m * CC + n] =
                    make_float2(acc[mt][nt][0], acc[mt][nt][1]);
                *(float2*)&Out[(size_t)(m + 8) * CC + n] =
                    make_float2(acc[mt][nt][2], acc[mt][nt][3]);
            }
        }
    }
}

// ---------------------------------------------------------------------------
// RoPE + bf16 hi/lo split of q/k/v.  q is pre-scaled by 1/sqrt(D).
// One thread per (bh, t, dim-pair i).
// ---------------------------------------------------------------------------
__device__ __forceinline__ void split_store(__nv_bfloat16* hi, __nv_bfloat16* lo,
                                            size_t idx, float x) {
    __nv_bfloat16 h = __float2bfloat16_rn(x);
    hi[idx] = h;
    lo[idx] = __float2bfloat16_rn(x - __bfloat162float(h));
}

__global__ __launch_bounds__(256)
void rope_kernel() {
    const int idx = blockIdx.x * blockDim.x + threadIdx.x;   // < BB*HH*TT*64
    const int i  = idx & 63;
    const int t  = (idx >> 6) & (TT - 1);
    const int bh = idx >> 18;
    if (bh >= BB * HH) return;

    const float inv_freq = 1.0f / powf(10000.0f, (float)(2 * i) / 128.0f);
    float s, c;
    sincosf((float)t * inv_freq, &s, &c);
    const float scale = 0.08838834764831845f;   // 1/sqrt(128)

    const size_t base = ((size_t)bh * TT + t) * DD;
    const float q0 = g_q[base + i], q1 = g_q[base + i + 64];
    const float qa = (q0 * c - q1 * s) * scale;
    const float qb = (q1 * c + q0 * s) * scale;
    split_store(g_qh, g_ql, base + i,      qa);
    split_store(g_qh, g_ql, base + i + 64, qb);

    const float k0 = g_k[base + i], k1 = g_k[base + i + 64];
    split_store(g_kh, g_kl, base + i,      k0 * c - k1 * s);
    split_store(g_kh, g_kl, base + i + 64, k1 * c + k0 * s);

    split_store(g_vh, g_vl, base + i,      g_v[base + i]);
    split_store(g_vh, g_vl, base + i + 64, g_v[base + i + 64]);
}

// ---------------------------------------------------------------------------
// Sliding-window causal flash attention on tensor cores.
// 128 threads (4 warps); q-tile 64 (warp = 16-row strip), kv chunk 64.
// S = Q K^T and O = P V via mma.sync bf16 with 3-term hi/lo split.
// Softmax entirely on register fragments (quad shfl reductions).
// ---------------------------------------------------------------------------
#define AROW 136                        // padded smem row stride in bf16
#define ATILE (64*AROW)                 // one 64x128 tile (elems)
#define ATTN_SMEM_BYTES (6*ATILE*2)     // Qh Ql Kh Kl Vh Vl = 104448 B

__global__ __launch_bounds__(128)
void attn_kernel() {
    extern __shared__ __nv_bfloat16 smA[];
    __nv_bfloat16* Qh = smA;
    __nv_bfloat16* Ql = smA + 1*ATILE;
    __nv_bfloat16* Kh = smA + 2*ATILE;
    __nv_bfloat16* Kl = smA + 3*ATILE;
    __nv_bfloat16* Vh = smA + 4*ATILE;
    __nv_bfloat16* Vl = smA + 5*ATILE;

    const int qb = blockIdx.x;          // 0..63
    const int bh = blockIdx.y;          // 0..15
    const int q0 = qb << 6;
    const int tid = threadIdx.x;
    const int warp = tid >> 5, lane = tid & 31;
    const int group = lane >> 2, tg = lane & 3;
    const int lq = lane & 7, lseg = lane >> 3;

    const size_t bhbase = (size_t)bh * TT * DD;

    // Load Q tile (rows q0..q0+63), hi and lo
    {
        const size_t qg = bhbase + (size_t)q0 * DD;
        for (int i = tid; i < 64 * 16; i += 128) {
            const int r = i >> 4, c8 = (i & 15) << 3;
            const size_t off = qg + (size_t)r * DD + c8;
            const int so = r * AROW + c8;
            *(uint4*)&Qh[so] = *(const uint4*)&g_qh[off];
            *(uint4*)&Ql[so] = *(const uint4*)&g_ql[off];
        }
    }

    // Fragment geometry (same proven mappings as gemm_bf16)
    const unsigned sb = (unsigned)__cvta_generic_to_shared(smA);
    const int aRow = lq + (lseg & 1) * 8;   // A tiles (and trans-V tiles)
    const int aCol = (lseg >> 1) * 8;
    const int bRow = lq + (lseg >> 1) * 8;  // non-trans B tiles (K)
    const int bCol = (lseg & 1) * 8;

    const unsigned qA = sb + 2u*(unsigned)((warp*16 + aRow)*AROW + aCol);
    const unsigned kA = sb + 2u*(unsigned)(2*ATILE) + 2u*(unsigned)(bRow*AROW + bCol);
    const unsigned vA = sb + 2u*(unsigned)(4*ATILE) + 2u*(unsigned)(aRow*AROW + aCol);

    float o[16][4];
    #pragma unroll
    for (int n = 0; n < 16; ++n)
        #pragma unroll
        for (int e = 0; e < 4; ++e) o[n][e] = 0.f;
    float mr0 = -1e30f, mr1 = -1e30f, lr0 = 0.f, lr1 = 0.f;

    const int qi0 = q0 + warp*16 + group;
    const int qi1 = qi0 + 8;

    int cb0 = qb - 8; if (cb0 < 0) cb0 = 0;
    for (int cb = cb0; cb <= qb; ++cb) {
        __syncthreads();      // previous iteration done with K/V
        {
            const size_t kg = bhbase + (size_t)(cb << 6) * DD;
            for (int i = tid; i < 64 * 16; i += 128) {
                const int r = i >> 4, c8 = (i & 15) << 3;
                const size_t off = kg + (size_t)r * DD + c8;
                const int so = r * AROW + c8;
                *(uint4*)&Kh[so] = *(const uint4*)&g_kh[off];
                *(uint4*)&Kl[so] = *(const uint4*)&g_kl[off];
                *(uint4*)&Vh[so] = *(const uint4*)&g_vh[off];
                *(uint4*)&Vl[so] = *(const uint4*)&g_vl[off];
            }
        }
        __syncthreads();

        // ---- S = Q K^T  (warp rows 16w..16w+15, keys 0..63 of chunk) ----
        float sacc[8][4];
        #pragma unroll
        for (int n = 0; n < 8; ++n)
            #pragma unroll
            for (int e = 0; e < 4; ++e) sacc[n][e] = 0.f;

        #pragma unroll
        for (int ks = 0; ks < 8; ++ks) {
            unsigned ah[4], al[4];
            LDSM4(ah, qA + 2u*(unsigned)(ks*16));
            LDSM4(al, qA + 2u*(unsigned)(ATILE + ks*16));
            #pragma unroll
            for (int p = 0; p < 4; ++p) {
                unsigned kh4[4], kl4[4];
                const unsigned ko = 2u*(unsigned)(p*16*AROW + ks*16);
                LDSM4(kh4, kA + ko);
                LDSM4(kl4, kA + 2u*(unsigned)ATILE + ko);
                #pragma unroll
                for (int sub = 0; sub < 2; ++sub) {
                    const int nt = 2*p + sub;
                    MMA16816(sacc[nt], ah, kh4[2*sub], kh4[2*sub+1]);
                    MMA16816(sacc[nt], ah, kl4[2*sub], kl4[2*sub+1]);
                    MMA16816(sacc[nt], al, kh4[2*sub], kh4[2*sub+1]);
                }
            }
        }

        // ---- mask (only edge chunks need it) ----
        if (cb == qb || cb == qb - 8) {
            const int kbase = cb << 6;
            #pragma unroll
            for (int nt = 0; nt < 8; ++nt) {
                const int kj0 = kbase + nt*8 + 2*tg, kj1 = kj0 + 1;
                if (!(kj0 <= qi0 && kj0 + WIN >= qi0)) sacc[nt][0] = -1e30f;
                if (!(kj1 <= qi0 && kj1 + WIN >= qi0)) sacc[nt][1] = -1e30f;
                if (!(kj0 <= qi1 && kj0 + WIN >= qi1)) sacc[nt][2] = -1e30f;
                if (!(kj1 <= qi1 && kj1 + WIN >= qi1)) sacc[nt][3] = -1e30f;
            }
        }

        // ---- online softmax on fragments ----
        float rm0 = -1e30f, rm1 = -1e30f;
        #pragma unroll
        for (int nt = 0; nt < 8; ++nt) {
            rm0 = fmaxf(rm0, fmaxf(sacc[nt][0], sacc[nt][1]));
            rm1 = fmaxf(rm1, fmaxf(sacc[nt][2], sacc[nt][3]));
        }
        rm0 = fmaxf(rm0, __shfl_xor_sync(0xffffffffu, rm0, 1));
        rm0 = fmaxf(rm0, __shfl_xor_sync(0xffffffffu, rm0, 2));
        rm1 = fmaxf(rm1, __shfl_xor_sync(0xffffffffu, rm1, 1));
        rm1 = fmaxf(rm1, __shfl_xor_sync(0xffffffffu, rm1, 2));

        const float mn0 = fmaxf(mr0, rm0), mn1 = fmaxf(mr1, rm1);
        const float c0 = __expf(mr0 - mn0), c1 = __expf(mr1 - mn1);
        mr0 = mn0; mr1 = mn1;

        float rs0 = 0.f, rs1 = 0.f;
        #pragma unroll
        for (int nt = 0; nt < 8; ++nt) {
            sacc[nt][0] = __expf(sacc[nt][0] - mn0); rs0 += sacc[nt][0];
            sacc[nt][1] = __expf(sacc[nt][1] - mn0); rs0 += sacc[nt][1];
            sacc[nt][2] = __expf(sacc[nt][2] - mn1); rs1 += sacc[nt][2];
            sacc[nt][3] = __expf(sacc[nt][3] - mn1); rs1 += sacc[nt][3];
        }
        rs0 += __shfl_xor_sync(0xffffffffu, rs0, 1);
        rs0 += __shfl_xor_sync(0xffffffffu, rs0, 2);
        rs1 += __shfl_xor_sync(0xffffffffu, rs1, 1);
        rs1 += __shfl_xor_sync(0xffffffffu, rs1, 2);
        lr0 = lr0 * c0 + rs0;
        lr1 = lr1 * c1 + rs1;

        #pragma unroll
        for (int n = 0; n < 16; ++n) {
            o[n][0] *= c0; o[n][1] *= c0;
            o[n][2] *= c1; o[n][3] *= c1;
        }

        // ---- O += P V  (P split hi/lo in registers; V via ldmatrix.trans) ----
        #pragma unroll
        for (int j = 0; j < 4; ++j) {
            unsigned ph[4], pl[4];
            #pragma unroll
            for (int e = 0; e < 4; ++e) {
                // e: 0->(rows g,  S[2j]),   1->(rows g+8, S[2j]),
                //    2->(rows g,  S[2j+1]), 3->(rows g+8, S[2j+1])
                const int nt = 2*j + (e >> 1);
                const int lo_i = (e & 1) ? 2 : 0;
                const float x = sacc[nt][lo_i], y = sacc[nt][lo_i + 1];
                const float xh = __bfloat162float(__float2bfloat16_rn(x));
                const float yh = __bfloat162float(__float2bfloat16_rn(y));
                ph[e] = pack_bf16x2(xh, yh);
                pl[e] = pack_bf16x2(x - xh, y - yh);
            }
            #pragma unroll
            for (int pp = 0; pp < 8; ++pp) {
                unsigned vh4[4], vl4[4];
                const unsigned vo = 2u*(unsigned)(j*16*AROW + pp*16);
                LDSM4T(vh4, vA + vo);
                LDSM4T(vl4, vA + 2u*(unsigned)ATILE + vo);
                #pragma unroll
                for (int sub = 0; sub < 2; ++sub) {
                    const int ntp = 2*pp + sub;
                    MMA16816(o[ntp], ph, vh4[2*sub], vh4[2*sub+1]);
                    MMA16816(o[ntp], ph, vl4[2*sub], vl4[2*sub+1]);
                    MMA16816(o[ntp], pl, vh4[2*sub], vh4[2*sub+1]);
                }
            }
        }
    }

    // ---- epilogue: normalize, write g_ao[b][t][h][d] ----
    const float inv0 = 1.f / lr0, inv1 = 1.f / lr1;
    const int b = bh >> 3, h = bh & 7;
    const size_t o0 = (((size_t)b * TT + qi0) * HH + h) * DD;
    const size_t o1 = (((size_t)b * TT + qi1) * HH + h) * DD;
    #pragma unroll
    for (int n = 0; n < 16; ++n) {
        const int d = n*8 + 2*tg;
        *(float2*)&g_ao[o0 + d] = make_float2(o[n][0]*inv0, o[n][1]*inv0);
        *(float2*)&g_ao[o1 + d] = make_float2(o[n][2]*inv1, o[n][3]*inv1);
    }
}

// ---------------------------------------------------------------------------
extern "C" void kernel_launch(void* const* d_in, const int* in_sizes, int n_in,
                              void* d_out, int out_size) {
    const float* x     = (const float*)d_in[0];   // [2,4096,1024]
    const float* w_qkv = (const float*)d_in[1];   // [3072,1024]
    const float* w_o   = (const float*)d_in[2];   // [1024,1024]
    float* out = (float*)d_out;                   // [2,4096,1024]

    cudaFuncSetAttribute(attn_kernel,
                         cudaFuncAttributeMaxDynamicSharedMemorySize,
                         ATTN_SMEM_BYTES);
    cudaFuncSetAttribute(gemm_bf16<0>,
                         cudaFuncAttributeMaxDynamicSharedMemorySize,
                         GEMM_SMEM_BYTES);
    cudaFuncSetAttribute(gemm_bf16<1>,
                         cudaFuncAttributeMaxDynamicSharedMemorySize,
                         GEMM_SMEM_BYTES);

    __nv_bfloat16 *p_xh, *p_xl, *p_wqh, *p_wql, *p_woh, *p_wol, *p_aoh, *p_aol;
    float* p_ao;
    cudaGetSymbolAddress((void**)&p_xh,  g_xh);
    cudaGetSymbolAddress((void**)&p_xl,  g_xl);
    cudaGetSymbolAddress((void**)&p_wqh, g_wqh);
    cudaGetSymbolAddress((void**)&p_wql, g_wql);
    cudaGetSymbolAddress((void**)&p_woh, g_woh);
    cudaGetSymbolAddress((void**)&p_wol, g_wol);
    cudaGetSymbolAddress((void**)&p_aoh, g_aoh);
    cudaGetSymbolAddress((void**)&p_aol, g_aol);
    cudaGetSymbolAddress((void**)&p_ao,  g_ao);

    // split inputs into bf16 hi/lo
    split_bf16<<<(MM*CC/4 + 255)/256, 256>>>(x,     p_xh,  p_xl,  MM*CC/4);
    split_bf16<<<(N3C*CC/4 + 255)/256, 256>>>(w_qkv, p_wqh, p_wql, N3C*CC/4);
    split_bf16<<<(CC*CC/4 + 255)/256, 256>>>(w_o,   p_woh, p_wol, CC*CC/4);

    gemm_bf16<0><<<dim3(N3C/128, MM/128), 512, GEMM_SMEM_BYTES>>>(nullptr);
    rope_kernel<<<(BB * HH * TT * 64) / 256, 256>>>();
    attn_kernel<<<dim3(TT/64, BB*HH), 128, ATTN_SMEM_BYTES>>>();

    split_bf16<<<(MM*CC/4 + 255)/256, 256>>>(p_ao, p_aoh, p_aol, MM*CC/4);
    gemm_bf16<1><<<dim3(CC/128, MM/128), 512, GEMM_SMEM_BYTES>>>(out);
}